// round 2
// baseline (speedup 1.0000x reference)
#include <cuda_runtime.h>
#include <cstdint>

#define NN   50000
#define EE   800000
#define INF  128
#define HH   256
#define H3   768
#define OUTF 2

// ---------------- scratch (static device globals; no allocations) ----------
__device__ float g_agg  [(size_t)NN * HH];   // aggregation buffer (max F=256)
__device__ float g_h    [(size_t)NN * HH];   // pre-BN hidden
__device__ float g_cat  [(size_t)NN * H3];   // concat(h1,h2,h3)
__device__ float g_mid  [(size_t)NN * H3];   // lin1 output
__device__ float g_sum  [HH];
__device__ float g_sumsq[HH];
__device__ float g_scale[HH];
__device__ float g_shift[HH];

// ---------------- edge scatter-sum: agg[dst] += x[src] ---------------------
// edge_index delivered as int32 by the harness (no int64 input path).
__global__ void agg_kernel(const float* __restrict__ x, int lda,
                           const int* __restrict__ ei,
                           float* __restrict__ agg, int F, int total)
{
    int idx = blockIdx.x * blockDim.x + threadIdx.x;
    if (idx >= total) return;
    int per = F >> 2;                // float4 chunks per row
    int e = idx / per;
    int c = idx - e * per;
    int s = ei[e];
    int d = ei[EE + e];
    float4 v = *(const float4*)(x + (size_t)s * lda + c * 4);
    float* p = agg + (size_t)d * F + c * 4;
    atomicAdd(p + 0, v.x);
    atomicAdd(p + 1, v.y);
    atomicAdd(p + 2, v.z);
    atomicAdd(p + 3, v.w);
}

// ---------------- tiled fp32 GEMM with fused A-transform / epilogue --------
// AMODE: 0 = A, 1 = A + A2, 2 = relu(A*scale[k]+shift[k])
// EPI:   0 = +bias,  1 = relu(+bias)
#define BM 64
#define BN 64
#define BK 16

template<int AMODE, int EPI>
__global__ __launch_bounds__(256)
void gemm_k(const float* __restrict__ A, int lda,
            const float* __restrict__ A2, int lda2,
            const float* __restrict__ W, int Nc,
            const float* __restrict__ bias,
            const float* __restrict__ scale, const float* __restrict__ shift,
            float* __restrict__ C, int ldc, int M, int K)
{
    __shared__ float As[BK][BM];
    __shared__ float Bs[BK][BN];

    int tid = threadIdx.x;
    int m0 = blockIdx.y * BM;
    int n0 = blockIdx.x * BN;
    int tx = tid & 15;
    int ty = tid >> 4;

    int arow = tid >> 2;            // 0..63
    int ac4  = (tid & 3) * 4;       // 0,4,8,12
    int brow = tid >> 4;            // 0..15
    int bc4  = (tid & 15) * 4;      // 0..60

    float acc[4][4] = {};

    for (int kt = 0; kt < K; kt += BK) {
        // A tile (transposed into As[k][m])
        int gr = m0 + arow;
        float4 av = make_float4(0.f, 0.f, 0.f, 0.f);
        if (gr < M) {
            av = *(const float4*)(A + (size_t)gr * lda + kt + ac4);
            if (AMODE == 1) {
                float4 b4 = *(const float4*)(A2 + (size_t)gr * lda2 + kt + ac4);
                av.x += b4.x; av.y += b4.y; av.z += b4.z; av.w += b4.w;
            } else if (AMODE == 2) {
                int k = kt + ac4;
                av.x = fmaxf(fmaf(av.x, scale[k+0], shift[k+0]), 0.f);
                av.y = fmaxf(fmaf(av.y, scale[k+1], shift[k+1]), 0.f);
                av.z = fmaxf(fmaf(av.z, scale[k+2], shift[k+2]), 0.f);
                av.w = fmaxf(fmaf(av.w, scale[k+3], shift[k+3]), 0.f);
            }
        }
        As[ac4 + 0][arow] = av.x;
        As[ac4 + 1][arow] = av.y;
        As[ac4 + 2][arow] = av.z;
        As[ac4 + 3][arow] = av.w;

        // B tile
        *(float4*)&Bs[brow][bc4] =
            *(const float4*)(W + (size_t)(kt + brow) * Nc + n0 + bc4);

        __syncthreads();

#pragma unroll
        for (int k = 0; k < BK; k++) {
            float4 af = *(const float4*)&As[k][ty * 4];
            float4 bf = *(const float4*)&Bs[k][tx * 4];
            float a[4] = {af.x, af.y, af.z, af.w};
            float b[4] = {bf.x, bf.y, bf.z, bf.w};
#pragma unroll
            for (int i = 0; i < 4; i++)
#pragma unroll
                for (int j = 0; j < 4; j++)
                    acc[i][j] = fmaf(a[i], b[j], acc[i][j]);
        }
        __syncthreads();
    }

#pragma unroll
    for (int i = 0; i < 4; i++) {
        int r = m0 + ty * 4 + i;
        if (r >= M) continue;
#pragma unroll
        for (int j = 0; j < 4; j++) {
            int c = n0 + tx * 4 + j;
            float v = acc[i][j] + bias[c];
            if (EPI) v = fmaxf(v, 0.f);
            C[(size_t)r * ldc + c] = v;
        }
    }
}

// ---------------- per-column stats over [M, 256] ----------------------------
__global__ void stats_kernel(const float* __restrict__ h, int M,
                             float* __restrict__ sum, float* __restrict__ sumsq)
{
    int col = threadIdx.x;                 // 256 threads = 256 columns
    int r0 = blockIdx.x * 128;
    int r1 = min(r0 + 128, M);
    float s = 0.f, s2 = 0.f;
    for (int r = r0; r < r1; r++) {
        float v = h[(size_t)r * HH + col];
        s  += v;
        s2 += v * v;
    }
    atomicAdd(&sum[col], s);
    atomicAdd(&sumsq[col], s2);
}

__global__ void bnfin_kernel(const float* __restrict__ g, const float* __restrict__ be,
                             const float* __restrict__ sum, const float* __restrict__ sumsq,
                             float* __restrict__ scale, float* __restrict__ shift)
{
    int c = threadIdx.x;
    const float invN = 1.f / (float)NN;
    float mu  = sum[c] * invN;
    float var = fmaxf(sumsq[c] * invN - mu * mu, 0.f);
    float sc  = g[c] * rsqrtf(var + 1e-5f);
    scale[c] = sc;
    shift[c] = be[c] - mu * sc;
}

// ---------------- lin2 (768x2) + softmax head --------------------------------
__global__ __launch_bounds__(256)
void head_kernel(const float* __restrict__ mid, const float* __restrict__ W,
                 const float* __restrict__ b, float* __restrict__ out,
                 int M, int half)
{
    __shared__ float ws[H3 * 2];
    for (int i = threadIdx.x; i < H3 * 2; i += blockDim.x) ws[i] = W[i];
    __syncthreads();

    int warp = (blockIdx.x * blockDim.x + threadIdx.x) >> 5;
    int lane = threadIdx.x & 31;
    if (warp >= M) return;

    const float* r = mid + (size_t)warp * H3;
    float a0 = 0.f, a1 = 0.f;
    for (int k = lane; k < H3; k += 32) {
        float v = r[k];
        a0 = fmaf(v, ws[2 * k + 0], a0);
        a1 = fmaf(v, ws[2 * k + 1], a1);
    }
#pragma unroll
    for (int o = 16; o; o >>= 1) {
        a0 += __shfl_down_sync(0xffffffffu, a0, o);
        a1 += __shfl_down_sync(0xffffffffu, a1, o);
    }
    if (lane == 0) {
        a0 += b[0];
        a1 += b[1];
        out[warp * 2 + 0] = a0;
        out[warp * 2 + 1] = a1;
        float m  = fmaxf(a0, a1);
        float e0 = expf(a0 - m);
        float e1 = expf(a1 - m);
        float inv = 1.f / (e0 + e1);
        out[half + warp * 2 + 0] = e0 * inv;
        out[half + warp * 2 + 1] = e1 * inv;
    }
}

// ---------------- host orchestration ----------------------------------------
static void run_layer(const float* xin, int lda_in, int Fin,
                      const int* ei,
                      const float* W1, const float* b1,
                      const float* gg, const float* be,
                      const float* W2, const float* b2,
                      float* agg, float* hbuf, float* cat_out,
                      float* sum, float* sumsq, float* scale, float* shift)
{
    cudaMemsetAsync(agg, 0, (size_t)NN * Fin * sizeof(float), 0);
    int total = EE * (Fin / 4);
    agg_kernel<<<(total + 255) / 256, 256>>>(xin, lda_in, ei, agg, Fin, total);

    dim3 grid1(HH / BN, (NN + BM - 1) / BM);
    gemm_k<1, 0><<<grid1, 256>>>(xin, lda_in, agg, Fin, W1, HH, b1,
                                 nullptr, nullptr, hbuf, HH, NN, Fin);

    cudaMemsetAsync(sum,   0, HH * sizeof(float), 0);
    cudaMemsetAsync(sumsq, 0, HH * sizeof(float), 0);
    stats_kernel<<<(NN + 127) / 128, HH>>>(hbuf, NN, sum, sumsq);
    bnfin_kernel<<<1, HH>>>(gg, be, sum, sumsq, scale, shift);

    gemm_k<2, 1><<<grid1, 256>>>(hbuf, HH, nullptr, 0, W2, HH, b2,
                                 scale, shift, cat_out, H3, NN, HH);
}

extern "C" void kernel_launch(void* const* d_in, const int* in_sizes, int n_in,
                              void* d_out, int out_size)
{
    const float* x  = (const float*)d_in[0];
    const int*   ei = (const int*)d_in[1];

    const float* c1_W1 = (const float*)d_in[2];
    const float* c1_b1 = (const float*)d_in[3];
    const float* c1_g  = (const float*)d_in[4];
    const float* c1_be = (const float*)d_in[5];
    const float* c1_W2 = (const float*)d_in[6];
    const float* c1_b2 = (const float*)d_in[7];

    const float* c2_W1 = (const float*)d_in[8];
    const float* c2_b1 = (const float*)d_in[9];
    const float* c2_g  = (const float*)d_in[10];
    const float* c2_be = (const float*)d_in[11];
    const float* c2_W2 = (const float*)d_in[12];
    const float* c2_b2 = (const float*)d_in[13];

    const float* c3_W1 = (const float*)d_in[14];
    const float* c3_b1 = (const float*)d_in[15];
    const float* c3_g  = (const float*)d_in[16];
    const float* c3_be = (const float*)d_in[17];
    const float* c3_W2 = (const float*)d_in[18];
    const float* c3_b2 = (const float*)d_in[19];

    const float* lin1_W = (const float*)d_in[20];
    const float* lin1_b = (const float*)d_in[21];
    const float* lin2_W = (const float*)d_in[22];
    const float* lin2_b = (const float*)d_in[23];

    float *agg, *hbuf, *cat, *mid, *sum, *sumsq, *scale, *shift;
    cudaGetSymbolAddress((void**)&agg,   g_agg);
    cudaGetSymbolAddress((void**)&hbuf,  g_h);
    cudaGetSymbolAddress((void**)&cat,   g_cat);
    cudaGetSymbolAddress((void**)&mid,   g_mid);
    cudaGetSymbolAddress((void**)&sum,   g_sum);
    cudaGetSymbolAddress((void**)&sumsq, g_sumsq);
    cudaGetSymbolAddress((void**)&scale, g_scale);
    cudaGetSymbolAddress((void**)&shift, g_shift);

    // layer 1: input x [N,128], output -> cat cols [0,256)
    run_layer(x, INF, INF, ei, c1_W1, c1_b1, c1_g, c1_be, c1_W2, c1_b2,
              agg, hbuf, cat + 0, sum, sumsq, scale, shift);
    // layer 2: input h1 (cat+0, lda=768), output -> cat cols [256,512)
    run_layer(cat + 0, H3, HH, ei, c2_W1, c2_b1, c2_g, c2_be, c2_W2, c2_b2,
              agg, hbuf, cat + HH, sum, sumsq, scale, shift);
    // layer 3: input h2 (cat+256), output -> cat cols [512,768)
    run_layer(cat + HH, H3, HH, ei, c3_W1, c3_b1, c3_g, c3_be, c3_W2, c3_b2,
              agg, hbuf, cat + 2 * HH, sum, sumsq, scale, shift);

    // readout lin1: [N,768] @ [768,768] + b, relu
    dim3 gridL(H3 / BN, (NN + BM - 1) / BM);
    gemm_k<0, 1><<<gridL, 256>>>(cat, H3, nullptr, 0, lin1_W, H3, lin1_b,
                                 nullptr, nullptr, mid, H3, NN, H3);

    // lin2 + softmax
    int half = out_size / 2;
    float* out = (float*)d_out;
    head_kernel<<<(NN * 32 + 255) / 256, 256>>>(mid, lin2_W, lin2_b, out, NN, half);
}

// round 3
// speedup vs baseline: 1.4515x; 1.4515x over previous
#include <cuda_runtime.h>
#include <cstdint>

#define NN   50000
#define EE   800000
#define INF  128
#define HH   256
#define H3   768
#define OUTF 2

// ---------------- scratch (static device globals; no allocations) ----------
__device__ float g_agg  [(size_t)NN * HH];
__device__ float g_h    [(size_t)NN * HH];
__device__ float g_cat  [(size_t)NN * H3];
__device__ float g_mid  [(size_t)NN * H3];
__device__ float g_sum  [HH];
__device__ float g_sumsq[HH];
__device__ float g_scale[HH];
__device__ float g_shift[HH];

// ---------------- edge scatter-sum: agg[dst] += x[src] ---------------------
// FLOG = log2(F/4) chunks per row; edge_index is int32 from the harness.
template<int FLOG>
__global__ void agg_kernel(const float* __restrict__ x, int lda,
                           const int* __restrict__ ei,
                           float* __restrict__ agg, int total)
{
    int idx = blockIdx.x * blockDim.x + threadIdx.x;
    if (idx >= total) return;
    const int F = 4 << FLOG;
    int e = idx >> FLOG;
    int c = idx & ((1 << FLOG) - 1);
    int s = ei[e];
    int d = ei[EE + e];
    float4 v = *(const float4*)(x + (size_t)s * lda + c * 4);
    float* p = agg + (size_t)d * F + c * 4;
    asm volatile("red.global.add.v4.f32 [%0], {%1, %2, %3, %4};"
                 :: "l"(p), "f"(v.x), "f"(v.y), "f"(v.z), "f"(v.w)
                 : "memory");
}

// ---------------- 128x128x8 fp32 GEMM, 8x8 microtile, reg-prefetch ----------
// AMODE: 0 = A, 1 = A + A2, 2 = relu(A*scale[k]+shift[k])
// EPI:   0 = +bias,  1 = relu(+bias)
#define BM 128
#define BN 128
#define BK 8

template<int AMODE, int EPI>
__global__ __launch_bounds__(256)
void gemm_k(const float* __restrict__ A, int lda,
            const float* __restrict__ A2, int lda2,
            const float* __restrict__ W, int Nc,
            const float* __restrict__ bias,
            const float* __restrict__ scale, const float* __restrict__ shift,
            float* __restrict__ C, int ldc, int M, int K)
{
    __shared__ float As[BK][BM];
    __shared__ float Bs[BK][BN];

    const int tid = threadIdx.x;
    const int m0 = blockIdx.y * BM;
    const int n0 = blockIdx.x * BN;

    // A tile load: 128 rows x 8 cols = 1024 floats, 256 threads x float4
    const int arow = tid >> 1;            // 0..127
    const int ak   = (tid & 1) * 4;       // 0 or 4
    // B tile load: 8 rows x 128 cols
    const int brow = tid >> 5;            // 0..7
    const int bc   = (tid & 31) * 4;      // 0..124
    // compute mapping: 16x16 threads, each 8x8 (split 4+4 with 64 offset)
    const int tx = tid & 15;
    const int ty = tid >> 4;

    const int garow = min(m0 + arow, M - 1);   // clamped (stores guarded later)
    const float* Arow  = A  + (size_t)garow * lda;
    const float* A2row = (AMODE == 1) ? A2 + (size_t)garow * lda2 : nullptr;
    const float* Brow  = W + (size_t)brow * Nc + n0 + bc;

    float acc[8][8] = {};

    // prologue: load first tiles into registers
    float4 va, vb;
    {
        va = *(const float4*)(Arow + ak);
        if (AMODE == 1) {
            float4 u = *(const float4*)(A2row + ak);
            va.x += u.x; va.y += u.y; va.z += u.z; va.w += u.w;
        } else if (AMODE == 2) {
            va.x = fmaxf(fmaf(va.x, scale[ak+0], shift[ak+0]), 0.f);
            va.y = fmaxf(fmaf(va.y, scale[ak+1], shift[ak+1]), 0.f);
            va.z = fmaxf(fmaf(va.z, scale[ak+2], shift[ak+2]), 0.f);
            va.w = fmaxf(fmaf(va.w, scale[ak+3], shift[ak+3]), 0.f);
        }
        vb = *(const float4*)(Brow);
    }

    for (int kt = 0; kt < K; kt += BK) {
        // commit prefetched tiles to smem
        As[ak + 0][arow] = va.x;
        As[ak + 1][arow] = va.y;
        As[ak + 2][arow] = va.z;
        As[ak + 3][arow] = va.w;
        *(float4*)&Bs[brow][bc] = vb;
        __syncthreads();

        // prefetch next tiles
        if (kt + BK < K) {
            int k = kt + BK + ak;
            va = *(const float4*)(Arow + k);
            if (AMODE == 1) {
                float4 u = *(const float4*)(A2row + k);
                va.x += u.x; va.y += u.y; va.z += u.z; va.w += u.w;
            } else if (AMODE == 2) {
                va.x = fmaxf(fmaf(va.x, scale[k+0], shift[k+0]), 0.f);
                va.y = fmaxf(fmaf(va.y, scale[k+1], shift[k+1]), 0.f);
                va.z = fmaxf(fmaf(va.z, scale[k+2], shift[k+2]), 0.f);
                va.w = fmaxf(fmaf(va.w, scale[k+3], shift[k+3]), 0.f);
            }
            vb = *(const float4*)(Brow + (kt + BK) * Nc);
        }

#pragma unroll
        for (int k = 0; k < BK; k++) {
            float4 a0 = *(const float4*)&As[k][ty * 4];
            float4 a1 = *(const float4*)&As[k][ty * 4 + 64];
            float4 b0 = *(const float4*)&Bs[k][tx * 4];
            float4 b1 = *(const float4*)&Bs[k][tx * 4 + 64];
            float a[8] = {a0.x, a0.y, a0.z, a0.w, a1.x, a1.y, a1.z, a1.w};
            float b[8] = {b0.x, b0.y, b0.z, b0.w, b1.x, b1.y, b1.z, b1.w};
#pragma unroll
            for (int i = 0; i < 8; i++)
#pragma unroll
                for (int j = 0; j < 8; j++)
                    acc[i][j] = fmaf(a[i], b[j], acc[i][j]);
        }
        __syncthreads();
    }

    // epilogue: bias (+relu), two float4 stores per row-half
    float bia[8];
#pragma unroll
    for (int j = 0; j < 4; j++) {
        bia[j]     = bias[n0 + tx * 4 + j];
        bia[j + 4] = bias[n0 + tx * 4 + 64 + j];
    }
#pragma unroll
    for (int ih = 0; ih < 2; ih++) {
#pragma unroll
        for (int i = 0; i < 4; i++) {
            int r = m0 + ty * 4 + ih * 64 + i;
            if (r >= M) continue;
            int ai = ih * 4 + i;
            float4 o0, o1;
            o0.x = acc[ai][0] + bia[0]; o0.y = acc[ai][1] + bia[1];
            o0.z = acc[ai][2] + bia[2]; o0.w = acc[ai][3] + bia[3];
            o1.x = acc[ai][4] + bia[4]; o1.y = acc[ai][5] + bia[5];
            o1.z = acc[ai][6] + bia[6]; o1.w = acc[ai][7] + bia[7];
            if (EPI) {
                o0.x = fmaxf(o0.x, 0.f); o0.y = fmaxf(o0.y, 0.f);
                o0.z = fmaxf(o0.z, 0.f); o0.w = fmaxf(o0.w, 0.f);
                o1.x = fmaxf(o1.x, 0.f); o1.y = fmaxf(o1.y, 0.f);
                o1.z = fmaxf(o1.z, 0.f); o1.w = fmaxf(o1.w, 0.f);
            }
            float* crow = C + (size_t)r * ldc + n0;
            *(float4*)(crow + tx * 4)      = o0;
            *(float4*)(crow + tx * 4 + 64) = o1;
        }
    }
}

// ---------------- per-column stats over [M, 256] ----------------------------
__global__ void stats_kernel(const float* __restrict__ h, int M,
                             float* __restrict__ sum, float* __restrict__ sumsq)
{
    int col = threadIdx.x;
    int r0 = blockIdx.x * 128;
    int r1 = min(r0 + 128, M);
    float s = 0.f, s2 = 0.f;
    for (int r = r0; r < r1; r++) {
        float v = h[(size_t)r * HH + col];
        s  += v;
        s2 += v * v;
    }
    atomicAdd(&sum[col], s);
    atomicAdd(&sumsq[col], s2);
}

__global__ void bnfin_kernel(const float* __restrict__ g, const float* __restrict__ be,
                             const float* __restrict__ sum, const float* __restrict__ sumsq,
                             float* __restrict__ scale, float* __restrict__ shift)
{
    int c = threadIdx.x;
    const float invN = 1.f / (float)NN;
    float mu  = sum[c] * invN;
    float var = fmaxf(sumsq[c] * invN - mu * mu, 0.f);
    float sc  = g[c] * rsqrtf(var + 1e-5f);
    scale[c] = sc;
    shift[c] = be[c] - mu * sc;
}

// ---------------- lin2 (768x2) + softmax head --------------------------------
__global__ __launch_bounds__(256)
void head_kernel(const float* __restrict__ mid, const float* __restrict__ W,
                 const float* __restrict__ b, float* __restrict__ out,
                 int M, int half)
{
    __shared__ float ws[H3 * 2];
    for (int i = threadIdx.x; i < H3 * 2; i += blockDim.x) ws[i] = W[i];
    __syncthreads();

    int warp = (blockIdx.x * blockDim.x + threadIdx.x) >> 5;
    int lane = threadIdx.x & 31;
    if (warp >= M) return;

    const float* r = mid + (size_t)warp * H3;
    float a0 = 0.f, a1 = 0.f;
    for (int k = lane; k < H3; k += 32) {
        float v = r[k];
        a0 = fmaf(v, ws[2 * k + 0], a0);
        a1 = fmaf(v, ws[2 * k + 1], a1);
    }
#pragma unroll
    for (int o = 16; o; o >>= 1) {
        a0 += __shfl_down_sync(0xffffffffu, a0, o);
        a1 += __shfl_down_sync(0xffffffffu, a1, o);
    }
    if (lane == 0) {
        a0 += b[0];
        a1 += b[1];
        out[warp * 2 + 0] = a0;
        out[warp * 2 + 1] = a1;
        float m  = fmaxf(a0, a1);
        float e0 = expf(a0 - m);
        float e1 = expf(a1 - m);
        float inv = 1.f / (e0 + e1);
        out[half + warp * 2 + 0] = e0 * inv;
        out[half + warp * 2 + 1] = e1 * inv;
    }
}

// ---------------- host orchestration ----------------------------------------
static void run_layer(const float* xin, int lda_in, int Fin,
                      const int* ei,
                      const float* W1, const float* b1,
                      const float* gg, const float* be,
                      const float* W2, const float* b2,
                      float* agg, float* hbuf, float* cat_out,
                      float* sum, float* sumsq, float* scale, float* shift)
{
    cudaMemsetAsync(agg, 0, (size_t)NN * Fin * sizeof(float), 0);
    int total = EE * (Fin / 4);
    if (Fin == 128)
        agg_kernel<5><<<(total + 255) / 256, 256>>>(xin, lda_in, ei, agg, total);
    else
        agg_kernel<6><<<(total + 255) / 256, 256>>>(xin, lda_in, ei, agg, total);

    dim3 grid1(HH / BN, (NN + BM - 1) / BM);
    gemm_k<1, 0><<<grid1, 256>>>(xin, lda_in, agg, Fin, W1, HH, b1,
                                 nullptr, nullptr, hbuf, HH, NN, Fin);

    cudaMemsetAsync(sum,   0, HH * sizeof(float), 0);
    cudaMemsetAsync(sumsq, 0, HH * sizeof(float), 0);
    stats_kernel<<<(NN + 127) / 128, HH>>>(hbuf, NN, sum, sumsq);
    bnfin_kernel<<<1, HH>>>(gg, be, sum, sumsq, scale, shift);

    gemm_k<2, 1><<<grid1, 256>>>(hbuf, HH, nullptr, 0, W2, HH, b2,
                                 scale, shift, cat_out, H3, NN, HH);
}

extern "C" void kernel_launch(void* const* d_in, const int* in_sizes, int n_in,
                              void* d_out, int out_size)
{
    const float* x  = (const float*)d_in[0];
    const int*   ei = (const int*)d_in[1];

    const float* c1_W1 = (const float*)d_in[2];
    const float* c1_b1 = (const float*)d_in[3];
    const float* c1_g  = (const float*)d_in[4];
    const float* c1_be = (const float*)d_in[5];
    const float* c1_W2 = (const float*)d_in[6];
    const float* c1_b2 = (const float*)d_in[7];

    const float* c2_W1 = (const float*)d_in[8];
    const float* c2_b1 = (const float*)d_in[9];
    const float* c2_g  = (const float*)d_in[10];
    const float* c2_be = (const float*)d_in[11];
    const float* c2_W2 = (const float*)d_in[12];
    const float* c2_b2 = (const float*)d_in[13];

    const float* c3_W1 = (const float*)d_in[14];
    const float* c3_b1 = (const float*)d_in[15];
    const float* c3_g  = (const float*)d_in[16];
    const float* c3_be = (const float*)d_in[17];
    const float* c3_W2 = (const float*)d_in[18];
    const float* c3_b2 = (const float*)d_in[19];

    const float* lin1_W = (const float*)d_in[20];
    const float* lin1_b = (const float*)d_in[21];
    const float* lin2_W = (const float*)d_in[22];
    const float* lin2_b = (const float*)d_in[23];

    float *agg, *hbuf, *cat, *mid, *sum, *sumsq, *scale, *shift;
    cudaGetSymbolAddress((void**)&agg,   g_agg);
    cudaGetSymbolAddress((void**)&hbuf,  g_h);
    cudaGetSymbolAddress((void**)&cat,   g_cat);
    cudaGetSymbolAddress((void**)&mid,   g_mid);
    cudaGetSymbolAddress((void**)&sum,   g_sum);
    cudaGetSymbolAddress((void**)&sumsq, g_sumsq);
    cudaGetSymbolAddress((void**)&scale, g_scale);
    cudaGetSymbolAddress((void**)&shift, g_shift);

    run_layer(x, INF, INF, ei, c1_W1, c1_b1, c1_g, c1_be, c1_W2, c1_b2,
              agg, hbuf, cat + 0, sum, sumsq, scale, shift);
    run_layer(cat + 0, H3, HH, ei, c2_W1, c2_b1, c2_g, c2_be, c2_W2, c2_b2,
              agg, hbuf, cat + HH, sum, sumsq, scale, shift);
    run_layer(cat + HH, H3, HH, ei, c3_W1, c3_b1, c3_g, c3_be, c3_W2, c3_b2,
              agg, hbuf, cat + 2 * HH, sum, sumsq, scale, shift);

    dim3 gridL(H3 / BN, (NN + BM - 1) / BM);
    gemm_k<0, 1><<<gridL, 256>>>(cat, H3, nullptr, 0, lin1_W, H3, lin1_b,
                                 nullptr, nullptr, mid, H3, NN, H3);

    int half = out_size / 2;
    float* out = (float*)d_out;
    head_kernel<<<(NN * 32 + 255) / 256, 256>>>(mid, lin2_W, lin2_b, out, NN, half);
}

// round 5
// speedup vs baseline: 1.6545x; 1.1398x over previous
#include <cuda_runtime.h>
#include <cstdint>

#define NN   50000
#define EE   800000
#define INF  128
#define HH   256
#define H3   768

// ---------------- scratch (static device globals; no allocations) ----------
__device__ float g_agg  [(size_t)NN * HH];
__device__ float g_h    [(size_t)NN * HH];
__device__ float g_cat  [(size_t)NN * H3];
__device__ float g_mid  [(size_t)NN * H3];
__device__ float g_sum  [HH];
__device__ float g_sumsq[HH];
__device__ float g_scale[HH];
__device__ float g_shift[HH];
__device__ int   g_deg  [NN];
__device__ int   g_off  [NN + 1];
__device__ int   g_cur  [NN];
__device__ int   g_col  [EE];

// ================= CSR build =================================================
__global__ void hist_k(const int* __restrict__ ei, int* __restrict__ deg)
{
    int e = blockIdx.x * blockDim.x + threadIdx.x;
    if (e < EE) atomicAdd(&deg[ei[EE + e]], 1);
}

__global__ void scan_k(const int* __restrict__ deg, int* __restrict__ off,
                       int* __restrict__ cur)
{
    __shared__ int wsum[32];
    __shared__ int carry;
    int tid = threadIdx.x, lane = tid & 31, w = tid >> 5;
    if (tid == 0) { carry = 0; off[0] = 0; }
    __syncthreads();
    for (int base = 0; base < NN; base += 1024) {
        int i = base + tid;
        int v = (i < NN) ? deg[i] : 0;
        int s = v;
#pragma unroll
        for (int o = 1; o < 32; o <<= 1) {
            int t = __shfl_up_sync(0xffffffffu, s, o);
            if (lane >= o) s += t;
        }
        if (lane == 31) wsum[w] = s;
        __syncthreads();
        if (w == 0) {
            int ws = wsum[lane];
#pragma unroll
            for (int o = 1; o < 32; o <<= 1) {
                int t = __shfl_up_sync(0xffffffffu, ws, o);
                if (lane >= o) ws += t;
            }
            wsum[lane] = ws;
        }
        __syncthreads();
        int inc = s + (w > 0 ? wsum[w - 1] : 0) + carry;
        if (i < NN) { off[i + 1] = inc; cur[i] = inc - v; }
        int tot = wsum[31];
        __syncthreads();
        if (tid == 0) carry += tot;
        __syncthreads();
    }
}

__global__ void fill_k(const int* __restrict__ ei, int* __restrict__ cur,
                       int* __restrict__ col)
{
    int e = blockIdx.x * blockDim.x + threadIdx.x;
    if (e < EE) {
        int p = atomicAdd(&cur[ei[EE + e]], 1);
        col[p] = ei[e];
    }
}

// ================= CSR gather aggregation (warp per node) ===================
template<int F>
__global__ __launch_bounds__(256)
void csr_agg(const float* __restrict__ x, int ldx,
             const int* __restrict__ off, const int* __restrict__ col,
             float* __restrict__ agg)
{
    int warp = (blockIdx.x * blockDim.x + threadIdx.x) >> 5;
    int lane = threadIdx.x & 31;
    if (warp >= NN) return;
    int o0 = off[warp], o1 = off[warp + 1];
    if (F == 128) {
        float4 a = {0.f, 0.f, 0.f, 0.f};
        int j = o0;
        for (; j + 1 < o1; j += 2) {
            const float4* r0 = (const float4*)(x + (size_t)col[j]     * ldx);
            const float4* r1 = (const float4*)(x + (size_t)col[j + 1] * ldx);
            float4 v0 = r0[lane], v1 = r1[lane];
            a.x += v0.x + v1.x; a.y += v0.y + v1.y;
            a.z += v0.z + v1.z; a.w += v0.w + v1.w;
        }
        if (j < o1) {
            float4 v = ((const float4*)(x + (size_t)col[j] * ldx))[lane];
            a.x += v.x; a.y += v.y; a.z += v.z; a.w += v.w;
        }
        ((float4*)(agg + (size_t)warp * 128))[lane] = a;
    } else {
        float4 a0 = {0.f,0.f,0.f,0.f}, a1 = {0.f,0.f,0.f,0.f};
        for (int j = o0; j < o1; j++) {
            const float4* r = (const float4*)(x + (size_t)col[j] * ldx);
            float4 v0 = r[lane], v1 = r[lane + 32];
            a0.x += v0.x; a0.y += v0.y; a0.z += v0.z; a0.w += v0.w;
            a1.x += v1.x; a1.y += v1.y; a1.z += v1.z; a1.w += v1.w;
        }
        float4* o = (float4*)(agg + (size_t)warp * 256);
        o[lane] = a0; o[lane + 32] = a1;
    }
}

// ================= tf32x3 tensor-core GEMM ==================================
__device__ __forceinline__ void tfsplit(float f, uint32_t& hi, uint32_t& lo)
{
    uint32_t h;
    asm("cvt.rna.tf32.f32 %0, %1;" : "=r"(h) : "f"(f));
    float l = f - __uint_as_float(h);      // tf32 bits are valid fp32
    uint32_t lw;
    asm("cvt.rna.tf32.f32 %0, %1;" : "=r"(lw) : "f"(l));
    hi = h; lo = lw;
}

__device__ __forceinline__ void mma8(float* c, const uint32_t* a, const uint32_t* b)
{
    asm volatile("mma.sync.aligned.m16n8k8.row.col.f32.tf32.tf32.f32 "
                 "{%0,%1,%2,%3}, {%4,%5,%6,%7}, {%8,%9}, {%0,%1,%2,%3};"
                 : "+f"(c[0]), "+f"(c[1]), "+f"(c[2]), "+f"(c[3])
                 : "r"(a[0]), "r"(a[1]), "r"(a[2]), "r"(a[3]),
                   "r"(b[0]), "r"(b[1]));
}

#define BM 128
#define BN 128
#define BK 16
#define LDA_S 20    // As[m][k] row stride (conflict-free loads & stores)
#define LDB_S 136   // Bs[k][n] row stride (conflict-free loads & stores)

// AMODE: 0 = A, 1 = A + A2, 2 = relu(A*scale[k]+shift[k]);  EPI: 1 = relu
template<int AMODE, int EPI>
__global__ __launch_bounds__(256)
void gemm_tc(const float* __restrict__ A, int lda,
             const float* __restrict__ A2, int lda2,
             const float* __restrict__ W, int Nc,
             const float* __restrict__ bias,
             const float* __restrict__ scale, const float* __restrict__ shift,
             float* __restrict__ C, int ldc, int M, int K)
{
    __shared__ __align__(16) float As[2][BM * LDA_S];
    __shared__ __align__(16) float Bs[2][BK * LDB_S];

    const int tid  = threadIdx.x;
    const int lane = tid & 31;
    const int wid  = tid >> 5;
    const int gid  = lane >> 2, tig = lane & 3;
    const int wm = (wid & 1) * 64;
    const int wn = (wid >> 1) * 32;
    const int m0 = blockIdx.y * BM;
    const int n0 = blockIdx.x * BN;

    // A gmem mapping: thread -> one m-row, 8 consecutive k
    const int am = tid >> 1;
    const int ak = (tid & 1) * 8;
    const int garow = min(m0 + am, M - 1);
    const float* Arow  = A + (size_t)garow * lda + ak;
    const float* A2row = (AMODE == 1) ? A2 + (size_t)garow * lda2 + ak : nullptr;
    // B gmem mapping: warp w -> k-rows 2w, 2w+1; lane covers 4 n
    const int bk0 = wid * 2;
    const float* Bbase = W + (size_t)bk0 * Nc + n0 + lane * 4;

    float acc[4][4][4];
#pragma unroll
    for (int i = 0; i < 4; i++)
#pragma unroll
        for (int j = 0; j < 4; j++)
#pragma unroll
            for (int k = 0; k < 4; k++) acc[i][j][k] = 0.f;

    float aP[8], bP[2][4];

    auto loadG = [&](int kt) {
        float4 u0 = *(const float4*)(Arow + kt);
        float4 u1 = *(const float4*)(Arow + kt + 4);
        aP[0]=u0.x; aP[1]=u0.y; aP[2]=u0.z; aP[3]=u0.w;
        aP[4]=u1.x; aP[5]=u1.y; aP[6]=u1.z; aP[7]=u1.w;
        if (AMODE == 1) {
            float4 w0 = *(const float4*)(A2row + kt);
            float4 w1 = *(const float4*)(A2row + kt + 4);
            aP[0]+=w0.x; aP[1]+=w0.y; aP[2]+=w0.z; aP[3]+=w0.w;
            aP[4]+=w1.x; aP[5]+=w1.y; aP[6]+=w1.z; aP[7]+=w1.w;
        } else if (AMODE == 2) {
            int kg = kt + ak;
#pragma unroll
            for (int j = 0; j < 8; j++)
                aP[j] = fmaxf(fmaf(aP[j], scale[kg + j], shift[kg + j]), 0.f);
        }
#pragma unroll
        for (int r = 0; r < 2; r++) {
            float4 v = *(const float4*)(Bbase + (size_t)(kt + r) * Nc);
            bP[r][0]=v.x; bP[r][1]=v.y; bP[r][2]=v.z; bP[r][3]=v.w;
        }
    };

    auto storeS = [&](int st) {
        *(float4*)&As[st][am * LDA_S + ak]     = make_float4(aP[0],aP[1],aP[2],aP[3]);
        *(float4*)&As[st][am * LDA_S + ak + 4] = make_float4(aP[4],aP[5],aP[6],aP[7]);
        *(float4*)&Bs[st][ bk0      * LDB_S + lane * 4] =
            make_float4(bP[0][0],bP[0][1],bP[0][2],bP[0][3]);
        *(float4*)&Bs[st][(bk0 + 1) * LDB_S + lane * 4] =
            make_float4(bP[1][0],bP[1][1],bP[1][2],bP[1][3]);
    };

    auto compute = [&](int st) {
#pragma unroll
        for (int kb = 0; kb < BK; kb += 8) {
            uint32_t ah[4][4], al[4][4], bh[4][2], bl[4][2];
#pragma unroll
            for (int mt = 0; mt < 4; mt++) {
                const float* p = &As[st][(wm + mt * 16 + gid) * LDA_S + kb + tig];
                tfsplit(p[0],              ah[mt][0], al[mt][0]);
                tfsplit(p[8 * LDA_S],      ah[mt][1], al[mt][1]);
                tfsplit(p[4],              ah[mt][2], al[mt][2]);
                tfsplit(p[8 * LDA_S + 4],  ah[mt][3], al[mt][3]);
            }
#pragma unroll
            for (int nt = 0; nt < 4; nt++) {
                const float* p = &Bs[st][(kb + tig) * LDB_S + wn + nt * 8 + gid];
                tfsplit(p[0],          bh[nt][0], bl[nt][0]);
                tfsplit(p[4 * LDB_S],  bh[nt][1], bl[nt][1]);
            }
#pragma unroll
            for (int mt = 0; mt < 4; mt++)
#pragma unroll
                for (int nt = 0; nt < 4; nt++) {
                    mma8(acc[mt][nt], al[mt], bh[nt]);
                    mma8(acc[mt][nt], ah[mt], bl[nt]);
                    mma8(acc[mt][nt], ah[mt], bh[nt]);
                }
        }
    };

    loadG(0);
    storeS(0);
    __syncthreads();
    int st = 0;
    for (int kt = 0; kt < K; kt += BK) {
        bool has = (kt + BK) < K;
        if (has) loadG(kt + BK);
        compute(st);
        if (has) storeS(st ^ 1);
        __syncthreads();
        st ^= 1;
    }

    // epilogue
#pragma unroll
    for (int nt = 0; nt < 4; nt++) {
        int cn = n0 + wn + nt * 8 + tig * 2;
        float b0 = bias[cn], b1 = bias[cn + 1];
#pragma unroll
        for (int mt = 0; mt < 4; mt++) {
            const float* c = acc[mt][nt];
            int r0 = m0 + wm + mt * 16 + gid;
            if (r0 < M) {
                float v0 = c[0] + b0, v1 = c[1] + b1;
                if (EPI) { v0 = fmaxf(v0, 0.f); v1 = fmaxf(v1, 0.f); }
                *(float2*)&C[(size_t)r0 * ldc + cn] = make_float2(v0, v1);
            }
            int r1 = r0 + 8;
            if (r1 < M) {
                float v0 = c[2] + b0, v1 = c[3] + b1;
                if (EPI) { v0 = fmaxf(v0, 0.f); v1 = fmaxf(v1, 0.f); }
                *(float2*)&C[(size_t)r1 * ldc + cn] = make_float2(v0, v1);
            }
        }
    }
}

// ================= BN stats ==================================================
__global__ void stats_kernel(const float* __restrict__ h, int M,
                             float* __restrict__ sum, float* __restrict__ sumsq)
{
    int col = threadIdx.x;
    int r0 = blockIdx.x * 128;
    int r1 = min(r0 + 128, M);
    float s = 0.f, s2 = 0.f;
    for (int r = r0; r < r1; r++) {
        float v = h[(size_t)r * HH + col];
        s  += v;
        s2 += v * v;
    }
    atomicAdd(&sum[col], s);
    atomicAdd(&sumsq[col], s2);
}

__global__ void bnfin_kernel(const float* __restrict__ g, const float* __restrict__ be,
                             const float* __restrict__ sum, const float* __restrict__ sumsq,
                             float* __restrict__ scale, float* __restrict__ shift)
{
    int c = threadIdx.x;
    const float invN = 1.f / (float)NN;
    float mu  = sum[c] * invN;
    float var = fmaxf(sumsq[c] * invN - mu * mu, 0.f);
    float sc  = g[c] * rsqrtf(var + 1e-5f);
    scale[c] = sc;
    shift[c] = be[c] - mu * sc;
}

// ================= lin2 + softmax head ======================================
__global__ __launch_bounds__(256)
void head_kernel(const float* __restrict__ mid, const float* __restrict__ W,
                 const float* __restrict__ b, float* __restrict__ out,
                 int M, int half)
{
    __shared__ float ws[H3 * 2];
    for (int i = threadIdx.x; i < H3 * 2; i += blockDim.x) ws[i] = W[i];
    __syncthreads();

    int warp = (blockIdx.x * blockDim.x + threadIdx.x) >> 5;
    int lane = threadIdx.x & 31;
    if (warp >= M) return;

    const float* r = mid + (size_t)warp * H3;
    float a0 = 0.f, a1 = 0.f;
    for (int k = lane; k < H3; k += 32) {
        float v = r[k];
        a0 = fmaf(v, ws[2 * k + 0], a0);
        a1 = fmaf(v, ws[2 * k + 1], a1);
    }
#pragma unroll
    for (int o = 16; o; o >>= 1) {
        a0 += __shfl_down_sync(0xffffffffu, a0, o);
        a1 += __shfl_down_sync(0xffffffffu, a1, o);
    }
    if (lane == 0) {
        a0 += b[0];
        a1 += b[1];
        out[warp * 2 + 0] = a0;
        out[warp * 2 + 1] = a1;
        float m  = fmaxf(a0, a1);
        float e0 = expf(a0 - m);
        float e1 = expf(a1 - m);
        float inv = 1.f / (e0 + e1);
        out[half + warp * 2 + 0] = e0 * inv;
        out[half + warp * 2 + 1] = e1 * inv;
    }
}

// ================= host orchestration =======================================
static void run_layer(const float* xin, int lda_in, int Fin,
                      const int* off, const int* col,
                      const float* W1, const float* b1,
                      const float* gg, const float* be,
                      const float* W2, const float* b2,
                      float* agg, float* hbuf, float* cat_out,
                      float* sum, float* sumsq, float* scale, float* shift)
{
    int aggBlocks = (NN + 7) / 8;
    if (Fin == 128)
        csr_agg<128><<<aggBlocks, 256>>>(xin, lda_in, off, col, agg);
    else
        csr_agg<256><<<aggBlocks, 256>>>(xin, lda_in, off, col, agg);

    dim3 g1(HH / BN, (NN + BM - 1) / BM);
    gemm_tc<1, 0><<<g1, 256>>>(xin, lda_in, agg, Fin, W1, HH, b1,
                               nullptr, nullptr, hbuf, HH, NN, Fin);

    cudaMemsetAsync(sum,   0, HH * sizeof(float), 0);
    cudaMemsetAsync(sumsq, 0, HH * sizeof(float), 0);
    stats_kernel<<<(NN + 127) / 128, HH>>>(hbuf, NN, sum, sumsq);
    bnfin_kernel<<<1, HH>>>(gg, be, sum, sumsq, scale, shift);

    gemm_tc<2, 1><<<g1, 256>>>(hbuf, HH, nullptr, 0, W2, HH, b2,
                               scale, shift, cat_out, H3, NN, HH);
}

extern "C" void kernel_launch(void* const* d_in, const int* in_sizes, int n_in,
                              void* d_out, int out_size)
{
    const float* x  = (const float*)d_in[0];
    const int*   ei = (const int*)d_in[1];

    const float* c1_W1 = (const float*)d_in[2];
    const float* c1_b1 = (const float*)d_in[3];
    const float* c1_g  = (const float*)d_in[4];
    const float* c1_be = (const float*)d_in[5];
    const float* c1_W2 = (const float*)d_in[6];
    const float* c1_b2 = (const float*)d_in[7];

    const float* c2_W1 = (const float*)d_in[8];
    const float* c2_b1 = (const float*)d_in[9];
    const float* c2_g  = (const float*)d_in[10];
    const float* c2_be = (const float*)d_in[11];
    const float* c2_W2 = (const float*)d_in[12];
    const float* c2_b2 = (const float*)d_in[13];

    const float* c3_W1 = (const float*)d_in[14];
    const float* c3_b1 = (const float*)d_in[15];
    const float* c3_g  = (const float*)d_in[16];
    const float* c3_be = (const float*)d_in[17];
    const float* c3_W2 = (const float*)d_in[18];
    const float* c3_b2 = (const float*)d_in[19];

    const float* lin1_W = (const float*)d_in[20];
    const float* lin1_b = (const float*)d_in[21];
    const float* lin2_W = (const float*)d_in[22];
    const float* lin2_b = (const float*)d_in[23];

    float *agg, *hbuf, *cat, *mid, *sum, *sumsq, *scale, *shift;
    int *deg, *off, *cur, *col;
    cudaGetSymbolAddress((void**)&agg,   g_agg);
    cudaGetSymbolAddress((void**)&hbuf,  g_h);
    cudaGetSymbolAddress((void**)&cat,   g_cat);
    cudaGetSymbolAddress((void**)&mid,   g_mid);
    cudaGetSymbolAddress((void**)&sum,   g_sum);
    cudaGetSymbolAddress((void**)&sumsq, g_sumsq);
    cudaGetSymbolAddress((void**)&scale, g_scale);
    cudaGetSymbolAddress((void**)&shift, g_shift);
    cudaGetSymbolAddress((void**)&deg,   g_deg);
    cudaGetSymbolAddress((void**)&off,   g_off);
    cudaGetSymbolAddress((void**)&cur,   g_cur);
    cudaGetSymbolAddress((void**)&col,   g_col);

    cudaMemsetAsync(deg, 0, NN * sizeof(int), 0);
    hist_k<<<(EE + 255) / 256, 256>>>(ei, deg);
    scan_k<<<1, 1024>>>(deg, off, cur);
    fill_k<<<(EE + 255) / 256, 256>>>(ei, cur, col);

    run_layer(x, INF, INF, off, col, c1_W1, c1_b1, c1_g, c1_be, c1_W2, c1_b2,
              agg, hbuf, cat + 0, sum, sumsq, scale, shift);
    run_layer(cat + 0, H3, HH, off, col, c2_W1, c2_b1, c2_g, c2_be, c2_W2, c2_b2,
              agg, hbuf, cat + HH, sum, sumsq, scale, shift);
    run_layer(cat + HH, H3, HH, off, col, c3_W1, c3_b1, c3_g, c3_be, c3_W2, c3_b2,
              agg, hbuf, cat + 2 * HH, sum, sumsq, scale, shift);

    dim3 gridL(H3 / BN, (NN + BM - 1) / BM);
    gemm_tc<0, 1><<<gridL, 256>>>(cat, H3, nullptr, 0, lin1_W, H3, lin1_b,
                                  nullptr, nullptr, mid, H3, NN, H3);

    int half = out_size / 2;
    float* out = (float*)d_out;
    head_kernel<<<(NN * 32 + 255) / 256, 256>>>(mid, lin2_W, lin2_b, out, NN, half);
}

// round 6
// speedup vs baseline: 2.9963x; 1.8110x over previous
#include <cuda_runtime.h>
#include <cuda_bf16.h>
#include <cstdint>

#define NN   50000
#define EE   800000
#define INF  128
#define HH   256
#define H3   768

// ---------------- scratch (static device globals; no allocations) ----------
__device__ float g_agg  [(size_t)NN * HH];
__device__ float g_h    [(size_t)NN * HH];
__device__ float g_cat  [(size_t)NN * H3];
__device__ float g_mid  [(size_t)NN * H3];
__device__ float g_sum  [HH];
__device__ float g_sumsq[HH];
__device__ float g_scale[HH];
__device__ float g_shift[HH];
__device__ int   g_deg  [NN];
__device__ int   g_off  [NN + 1];
__device__ int   g_cur  [NN];
__device__ int   g_col  [EE];

// ================= CSR build =================================================
__global__ void hist_k(const int* __restrict__ ei, int* __restrict__ deg)
{
    int e = blockIdx.x * blockDim.x + threadIdx.x;
    if (e < EE) atomicAdd(&deg[ei[EE + e]], 1);
}

__global__ void scan_k(const int* __restrict__ deg, int* __restrict__ off,
                       int* __restrict__ cur)
{
    __shared__ int wsum[32];
    __shared__ int carry;
    int tid = threadIdx.x, lane = tid & 31, w = tid >> 5;
    if (tid == 0) { carry = 0; off[0] = 0; }
    __syncthreads();
    for (int base = 0; base < NN; base += 1024) {
        int i = base + tid;
        int v = (i < NN) ? deg[i] : 0;
        int s = v;
#pragma unroll
        for (int o = 1; o < 32; o <<= 1) {
            int t = __shfl_up_sync(0xffffffffu, s, o);
            if (lane >= o) s += t;
        }
        if (lane == 31) wsum[w] = s;
        __syncthreads();
        if (w == 0) {
            int ws = wsum[lane];
#pragma unroll
            for (int o = 1; o < 32; o <<= 1) {
                int t = __shfl_up_sync(0xffffffffu, ws, o);
                if (lane >= o) ws += t;
            }
            wsum[lane] = ws;
        }
        __syncthreads();
        int inc = s + (w > 0 ? wsum[w - 1] : 0) + carry;
        if (i < NN) { off[i + 1] = inc; cur[i] = inc - v; }
        int tot = wsum[31];
        __syncthreads();
        if (tid == 0) carry += tot;
        __syncthreads();
    }
}

__global__ void fill_k(const int* __restrict__ ei, int* __restrict__ cur,
                       int* __restrict__ col)
{
    int e = blockIdx.x * blockDim.x + threadIdx.x;
    if (e < EE) {
        int p = atomicAdd(&cur[ei[EE + e]], 1);
        col[p] = ei[e];
    }
}

// ================= CSR gather aggregation (warp per node) ===================
template<int F>
__global__ __launch_bounds__(256)
void csr_agg(const float* __restrict__ x, int ldx,
             const int* __restrict__ off, const int* __restrict__ col,
             float* __restrict__ agg)
{
    int warp = (blockIdx.x * blockDim.x + threadIdx.x) >> 5;
    int lane = threadIdx.x & 31;
    if (warp >= NN) return;
    int o0 = off[warp], o1 = off[warp + 1];
    if (F == 128) {
        float4 a = {0.f, 0.f, 0.f, 0.f};
        int j = o0;
        for (; j + 1 < o1; j += 2) {
            const float4* r0 = (const float4*)(x + (size_t)col[j]     * ldx);
            const float4* r1 = (const float4*)(x + (size_t)col[j + 1] * ldx);
            float4 v0 = r0[lane], v1 = r1[lane];
            a.x += v0.x + v1.x; a.y += v0.y + v1.y;
            a.z += v0.z + v1.z; a.w += v0.w + v1.w;
        }
        if (j < o1) {
            float4 v = ((const float4*)(x + (size_t)col[j] * ldx))[lane];
            a.x += v.x; a.y += v.y; a.z += v.z; a.w += v.w;
        }
        ((float4*)(agg + (size_t)warp * 128))[lane] = a;
    } else {
        float4 a0 = {0.f,0.f,0.f,0.f}, a1 = {0.f,0.f,0.f,0.f};
        for (int j = o0; j < o1; j++) {
            const float4* r = (const float4*)(x + (size_t)col[j] * ldx);
            float4 v0 = r[lane], v1 = r[lane + 32];
            a0.x += v0.x; a0.y += v0.y; a0.z += v0.z; a0.w += v0.w;
            a1.x += v1.x; a1.y += v1.y; a1.z += v1.z; a1.w += v1.w;
        }
        float4* o = (float4*)(agg + (size_t)warp * 256);
        o[lane] = a0; o[lane + 32] = a1;
    }
}

// ================= bf16x3 tensor-core GEMM ==================================
__device__ __forceinline__ uint32_t pk2(__nv_bfloat16 lo, __nv_bfloat16 hi)
{
    __nv_bfloat162 t;
    t.x = lo; t.y = hi;
    return *reinterpret_cast<uint32_t*>(&t);
}

// split (v0=k-even, v1=k-odd) into packed hi word + packed residual word
__device__ __forceinline__ void bfsplit2(float v0, float v1,
                                         uint32_t& hw, uint32_t& lw)
{
    __nv_bfloat16 h0 = __float2bfloat16(v0);
    __nv_bfloat16 h1 = __float2bfloat16(v1);
    float l0 = v0 - __bfloat162float(h0);
    float l1 = v1 - __bfloat162float(h1);
    hw = pk2(h0, h1);
    lw = pk2(__float2bfloat16(l0), __float2bfloat16(l1));
}

__device__ __forceinline__ void mma16(float* c, const uint32_t* a, const uint32_t* b)
{
    asm volatile("mma.sync.aligned.m16n8k16.row.col.f32.bf16.bf16.f32 "
                 "{%0,%1,%2,%3}, {%4,%5,%6,%7}, {%8,%9}, {%0,%1,%2,%3};"
                 : "+f"(c[0]), "+f"(c[1]), "+f"(c[2]), "+f"(c[3])
                 : "r"(a[0]), "r"(a[1]), "r"(a[2]), "r"(a[3]),
                   "r"(b[0]), "r"(b[1]));
}

#define BM 128
#define BN 128
#define BK 16
#define LDA_W 12    // words (bf16x2) per A row in smem: 8 used + pad -> conflict-free
#define LDB_W 136   // words per B k2-row: 128 used + 8 pad -> conflict-free

// AMODE: 0 = A, 1 = A + A2, 2 = relu(A*scale[k]+shift[k]);  EPI: 1 = relu
template<int AMODE, int EPI>
__global__ __launch_bounds__(256)
void gemm_tc(const float* __restrict__ A, int lda,
             const float* __restrict__ A2, int lda2,
             const float* __restrict__ W, int Nc,
             const float* __restrict__ bias,
             const float* __restrict__ scale, const float* __restrict__ shift,
             float* __restrict__ C, int ldc, int M, int K)
{
    __shared__ __align__(16) uint32_t AsH[2][BM * LDA_W];
    __shared__ __align__(16) uint32_t AsL[2][BM * LDA_W];
    __shared__ __align__(16) uint32_t BsH[2][8 * LDB_W];
    __shared__ __align__(16) uint32_t BsL[2][8 * LDB_W];

    const int tid  = threadIdx.x;
    const int lane = tid & 31;
    const int wid  = tid >> 5;
    const int gid  = lane >> 2, tig = lane & 3;
    const int wm = (wid & 1) * 64;
    const int wn = (wid >> 1) * 32;
    const int m0 = blockIdx.y * BM;
    const int n0 = blockIdx.x * BN;

    // A gmem mapping: thread -> one m-row, 8 consecutive k
    const int am = tid >> 1;
    const int ak = (tid & 1) * 8;         // k offset (elements)
    const int aw = ak >> 1;               // word offset (0 or 4)
    const int garow = min(m0 + am, M - 1);
    const float* Arow  = A + (size_t)garow * lda + ak;
    const float* A2row = (AMODE == 1) ? A2 + (size_t)garow * lda2 + ak : nullptr;
    // B gmem mapping: warp w -> k-rows 2w, 2w+1; lane covers 4 n
    const float* Bbase = W + (size_t)(2 * wid) * Nc + n0 + lane * 4;

    float acc[4][4][4];
#pragma unroll
    for (int i = 0; i < 4; i++)
#pragma unroll
        for (int j = 0; j < 4; j++)
#pragma unroll
            for (int k = 0; k < 4; k++) acc[i][j][k] = 0.f;

    float aP[8];
    float bP[2][4];

    auto loadG = [&](int kt) {
        float4 u0 = *(const float4*)(Arow + kt);
        float4 u1 = *(const float4*)(Arow + kt + 4);
        aP[0]=u0.x; aP[1]=u0.y; aP[2]=u0.z; aP[3]=u0.w;
        aP[4]=u1.x; aP[5]=u1.y; aP[6]=u1.z; aP[7]=u1.w;
        if (AMODE == 1) {
            float4 w0 = *(const float4*)(A2row + kt);
            float4 w1 = *(const float4*)(A2row + kt + 4);
            aP[0]+=w0.x; aP[1]+=w0.y; aP[2]+=w0.z; aP[3]+=w0.w;
            aP[4]+=w1.x; aP[5]+=w1.y; aP[6]+=w1.z; aP[7]+=w1.w;
        } else if (AMODE == 2) {
            int kg = kt + ak;
#pragma unroll
            for (int j = 0; j < 8; j++)
                aP[j] = fmaxf(fmaf(aP[j], scale[kg + j], shift[kg + j]), 0.f);
        }
        float4 v0 = *(const float4*)(Bbase + (size_t)kt * Nc);
        float4 v1 = *(const float4*)(Bbase + (size_t)(kt + 1) * Nc);
        bP[0][0]=v0.x; bP[0][1]=v0.y; bP[0][2]=v0.z; bP[0][3]=v0.w;
        bP[1][0]=v1.x; bP[1][1]=v1.y; bP[1][2]=v1.z; bP[1][3]=v1.w;
    };

    auto storeS = [&](int st) {
        uint32_t ah[4], al[4];
#pragma unroll
        for (int j = 0; j < 4; j++)
            bfsplit2(aP[2*j], aP[2*j+1], ah[j], al[j]);
        *(uint4*)&AsH[st][am * LDA_W + aw] = *(uint4*)ah;
        *(uint4*)&AsL[st][am * LDA_W + aw] = *(uint4*)al;
        uint32_t bh[4], bl[4];
#pragma unroll
        for (int j = 0; j < 4; j++)
            bfsplit2(bP[0][j], bP[1][j], bh[j], bl[j]);   // lo half = k even row
        *(uint4*)&BsH[st][wid * LDB_W + lane * 4] = *(uint4*)bh;
        *(uint4*)&BsL[st][wid * LDB_W + lane * 4] = *(uint4*)bl;
    };

    auto compute = [&](int st) {
        uint32_t aH[4][4], aL[4][4], bH[4][2], bL[4][2];
#pragma unroll
        for (int mt = 0; mt < 4; mt++) {
            int r0 = (wm + mt * 16 + gid) * LDA_W;
            int r8 = r0 + 8 * LDA_W;
            aH[mt][0] = AsH[st][r0 + tig];
            aH[mt][1] = AsH[st][r8 + tig];
            aH[mt][2] = AsH[st][r0 + tig + 4];
            aH[mt][3] = AsH[st][r8 + tig + 4];
            aL[mt][0] = AsL[st][r0 + tig];
            aL[mt][1] = AsL[st][r8 + tig];
            aL[mt][2] = AsL[st][r0 + tig + 4];
            aL[mt][3] = AsL[st][r8 + tig + 4];
        }
#pragma unroll
        for (int nt = 0; nt < 4; nt++) {
            int n = wn + nt * 8 + gid;
            bH[nt][0] = BsH[st][ tig      * LDB_W + n];
            bH[nt][1] = BsH[st][(tig + 4) * LDB_W + n];
            bL[nt][0] = BsL[st][ tig      * LDB_W + n];
            bL[nt][1] = BsL[st][(tig + 4) * LDB_W + n];
        }
#pragma unroll
        for (int mt = 0; mt < 4; mt++)
#pragma unroll
            for (int nt = 0; nt < 4; nt++) {
                mma16(acc[mt][nt], aL[mt], bH[nt]);
                mma16(acc[mt][nt], aH[mt], bL[nt]);
                mma16(acc[mt][nt], aH[mt], bH[nt]);
            }
    };

    loadG(0);
    storeS(0);
    __syncthreads();
    int st = 0;
    for (int kt = 0; kt < K; kt += BK) {
        bool has = (kt + BK) < K;
        if (has) loadG(kt + BK);
        compute(st);
        if (has) storeS(st ^ 1);
        __syncthreads();
        st ^= 1;
    }

    // epilogue
#pragma unroll
    for (int nt = 0; nt < 4; nt++) {
        int cn = n0 + wn + nt * 8 + tig * 2;
        float b0 = bias[cn], b1 = bias[cn + 1];
#pragma unroll
        for (int mt = 0; mt < 4; mt++) {
            const float* c = acc[mt][nt];
            int r0 = m0 + wm + mt * 16 + gid;
            if (r0 < M) {
                float v0 = c[0] + b0, v1 = c[1] + b1;
                if (EPI) { v0 = fmaxf(v0, 0.f); v1 = fmaxf(v1, 0.f); }
                *(float2*)&C[(size_t)r0 * ldc + cn] = make_float2(v0, v1);
            }
            int r1 = r0 + 8;
            if (r1 < M) {
                float v0 = c[2] + b0, v1 = c[3] + b1;
                if (EPI) { v0 = fmaxf(v0, 0.f); v1 = fmaxf(v1, 0.f); }
                *(float2*)&C[(size_t)r1 * ldc + cn] = make_float2(v0, v1);
            }
        }
    }
}

// ================= BN stats ==================================================
__global__ void stats_kernel(const float* __restrict__ h, int M,
                             float* __restrict__ sum, float* __restrict__ sumsq)
{
    int col = threadIdx.x;
    int r0 = blockIdx.x * 128;
    int r1 = min(r0 + 128, M);
    float s = 0.f, s2 = 0.f;
    for (int r = r0; r < r1; r++) {
        float v = h[(size_t)r * HH + col];
        s  += v;
        s2 += v * v;
    }
    atomicAdd(&sum[col], s);
    atomicAdd(&sumsq[col], s2);
}

__global__ void bnfin_kernel(const float* __restrict__ g, const float* __restrict__ be,
                             const float* __restrict__ sum, const float* __restrict__ sumsq,
                             float* __restrict__ scale, float* __restrict__ shift)
{
    int c = threadIdx.x;
    const float invN = 1.f / (float)NN;
    float mu  = sum[c] * invN;
    float var = fmaxf(sumsq[c] * invN - mu * mu, 0.f);
    float sc  = g[c] * rsqrtf(var + 1e-5f);
    scale[c] = sc;
    shift[c] = be[c] - mu * sc;
}

// ================= lin2 + softmax head ======================================
__global__ __launch_bounds__(256)
void head_kernel(const float* __restrict__ mid, const float* __restrict__ W,
                 const float* __restrict__ b, float* __restrict__ out,
                 int M, int half)
{
    __shared__ float ws[H3 * 2];
    for (int i = threadIdx.x; i < H3 * 2; i += blockDim.x) ws[i] = W[i];
    __syncthreads();

    int warp = (blockIdx.x * blockDim.x + threadIdx.x) >> 5;
    int lane = threadIdx.x & 31;
    if (warp >= M) return;

    const float* r = mid + (size_t)warp * H3;
    float a0 = 0.f, a1 = 0.f;
    for (int k = lane; k < H3; k += 32) {
        float v = r[k];
        a0 = fmaf(v, ws[2 * k + 0], a0);
        a1 = fmaf(v, ws[2 * k + 1], a1);
    }
#pragma unroll
    for (int o = 16; o; o >>= 1) {
        a0 += __shfl_down_sync(0xffffffffu, a0, o);
        a1 += __shfl_down_sync(0xffffffffu, a1, o);
    }
    if (lane == 0) {
        a0 += b[0];
        a1 += b[1];
        out[warp * 2 + 0] = a0;
        out[warp * 2 + 1] = a1;
        float m  = fmaxf(a0, a1);
        float e0 = expf(a0 - m);
        float e1 = expf(a1 - m);
        float inv = 1.f / (e0 + e1);
        out[half + warp * 2 + 0] = e0 * inv;
        out[half + warp * 2 + 1] = e1 * inv;
    }
}

// ================= host orchestration =======================================
static void run_layer(const float* xin, int lda_in, int Fin,
                      const int* off, const int* col,
                      const float* W1, const float* b1,
                      const float* gg, const float* be,
                      const float* W2, const float* b2,
                      float* agg, float* hbuf, float* cat_out,
                      float* sum, float* sumsq, float* scale, float* shift)
{
    int aggBlocks = (NN + 7) / 8;
    if (Fin == 128)
        csr_agg<128><<<aggBlocks, 256>>>(xin, lda_in, off, col, agg);
    else
        csr_agg<256><<<aggBlocks, 256>>>(xin, lda_in, off, col, agg);

    dim3 g1(HH / BN, (NN + BM - 1) / BM);
    gemm_tc<1, 0><<<g1, 256>>>(xin, lda_in, agg, Fin, W1, HH, b1,
                               nullptr, nullptr, hbuf, HH, NN, Fin);

    cudaMemsetAsync(sum,   0, HH * sizeof(float), 0);
    cudaMemsetAsync(sumsq, 0, HH * sizeof(float), 0);
    stats_kernel<<<(NN + 127) / 128, HH>>>(hbuf, NN, sum, sumsq);
    bnfin_kernel<<<1, HH>>>(gg, be, sum, sumsq, scale, shift);

    gemm_tc<2, 1><<<g1, 256>>>(hbuf, HH, nullptr, 0, W2, HH, b2,
                               scale, shift, cat_out, H3, NN, HH);
}

extern "C" void kernel_launch(void* const* d_in, const int* in_sizes, int n_in,
                              void* d_out, int out_size)
{
    const float* x  = (const float*)d_in[0];
    const int*   ei = (const int*)d_in[1];

    const float* c1_W1 = (const float*)d_in[2];
    const float* c1_b1 = (const float*)d_in[3];
    const float* c1_g  = (const float*)d_in[4];
    const float* c1_be = (const float*)d_in[5];
    const float* c1_W2 = (const float*)d_in[6];
    const float* c1_b2 = (const float*)d_in[7];

    const float* c2_W1 = (const float*)d_in[8];
    const float* c2_b1 = (const float*)d_in[9];
    const float* c2_g  = (const float*)d_in[10];
    const float* c2_be = (const float*)d_in[11];
    const float* c2_W2 = (const float*)d_in[12];
    const float* c2_b2 = (const float*)d_in[13];

    const float* c3_W1 = (const float*)d_in[14];
    const float* c3_b1 = (const float*)d_in[15];
    const float* c3_g  = (const float*)d_in[16];
    const float* c3_be = (const float*)d_in[17];
    const float* c3_W2 = (const float*)d_in[18];
    const float* c3_b2 = (const float*)d_in[19];

    const float* lin1_W = (const float*)d_in[20];
    const float* lin1_b = (const float*)d_in[21];
    const float* lin2_W = (const float*)d_in[22];
    const float* lin2_b = (const float*)d_in[23];

    float *agg, *hbuf, *cat, *mid, *sum, *sumsq, *scale, *shift;
    int *deg, *off, *cur, *col;
    cudaGetSymbolAddress((void**)&agg,   g_agg);
    cudaGetSymbolAddress((void**)&hbuf,  g_h);
    cudaGetSymbolAddress((void**)&cat,   g_cat);
    cudaGetSymbolAddress((void**)&mid,   g_mid);
    cudaGetSymbolAddress((void**)&sum,   g_sum);
    cudaGetSymbolAddress((void**)&sumsq, g_sumsq);
    cudaGetSymbolAddress((void**)&scale, g_scale);
    cudaGetSymbolAddress((void**)&shift, g_shift);
    cudaGetSymbolAddress((void**)&deg,   g_deg);
    cudaGetSymbolAddress((void**)&off,   g_off);
    cudaGetSymbolAddress((void**)&cur,   g_cur);
    cudaGetSymbolAddress((void**)&col,   g_col);

    cudaMemsetAsync(deg, 0, NN * sizeof(int), 0);
    hist_k<<<(EE + 255) / 256, 256>>>(ei, deg);
    scan_k<<<1, 1024>>>(deg, off, cur);
    fill_k<<<(EE + 255) / 256, 256>>>(ei, cur, col);

    run_layer(x, INF, INF, off, col, c1_W1, c1_b1, c1_g, c1_be, c1_W2, c1_b2,
              agg, hbuf, cat + 0, sum, sumsq, scale, shift);
    run_layer(cat + 0, H3, HH, off, col, c2_W1, c2_b1, c2_g, c2_be, c2_W2, c2_b2,
              agg, hbuf, cat + HH, sum, sumsq, scale, shift);
    run_layer(cat + HH, H3, HH, off, col, c3_W1, c3_b1, c3_g, c3_be, c3_W2, c3_b2,
              agg, hbuf, cat + 2 * HH, sum, sumsq, scale, shift);

    dim3 gridL(H3 / BN, (NN + BM - 1) / BM);
    gemm_tc<0, 1><<<gridL, 256>>>(cat, H3, nullptr, 0, lin1_W, H3, lin1_b,
                                  nullptr, nullptr, mid, H3, NN, H3);

    int half = out_size / 2;
    float* out = (float*)d_out;
    head_kernel<<<(NN * 32 + 255) / 256, 256>>>(mid, lin2_W, lin2_b, out, NN, half);
}

// round 7
// speedup vs baseline: 3.0052x; 1.0030x over previous
#include <cuda_runtime.h>
#include <cuda_bf16.h>
#include <cstdint>

#define NN   50000
#define EE   800000
#define INF  128
#define HH   256
#define H3   768

// ---------------- scratch (static device globals; no allocations) ----------
__device__ float    g_h    [(size_t)NN * HH];          // pre-BN hidden (fp32)
__device__ float    g_cat  [(size_t)NN * H3];          // fp32 concat (agg input + head staging source)
__device__ float    g_mid  [(size_t)NN * H3];          // lin1 output (fp32)
__device__ uint32_t g_aggH [(size_t)NN * 128];         // split (x+agg), packed k-pairs
__device__ uint32_t g_aggL [(size_t)NN * 128];
__device__ uint32_t g_hH   [(size_t)NN * 128];         // split relu(bn(h))
__device__ uint32_t g_hL   [(size_t)NN * 128];
__device__ uint32_t g_catH [(size_t)NN * 384];         // split concat(h1,h2,h3)
__device__ uint32_t g_catL [(size_t)NN * 384];
__device__ uint32_t g_WH   [475136];                   // split weights (all 7 mats)
__device__ uint32_t g_WL   [475136];
__device__ float    g_sum  [HH];
__device__ float    g_sumsq[HH];
__device__ float    g_scale[HH];
__device__ float    g_shift[HH];
__device__ int      g_deg  [NN];
__device__ int      g_off  [NN + 1];
__device__ int      g_cur  [NN];
__device__ int      g_col  [EE];

#define W_C1W1 0
#define W_C1W2 16384
#define W_C2W1 49152
#define W_C2W2 81920
#define W_C3W1 114688
#define W_C3W2 147456
#define W_LIN1 180224

// ---------------- bf16 split helpers ----------------------------------------
__device__ __forceinline__ uint32_t pk2(__nv_bfloat16 lo, __nv_bfloat16 hi)
{
    __nv_bfloat162 t; t.x = lo; t.y = hi;
    return *reinterpret_cast<uint32_t*>(&t);
}
__device__ __forceinline__ void bfsplit2(float v0, float v1,
                                         uint32_t& hw, uint32_t& lw)
{
    __nv_bfloat16 h0 = __float2bfloat16(v0);
    __nv_bfloat16 h1 = __float2bfloat16(v1);
    float l0 = v0 - __bfloat162float(h0);
    float l1 = v1 - __bfloat162float(h1);
    hw = pk2(h0, h1);
    lw = pk2(__float2bfloat16(l0), __float2bfloat16(l1));
}

// ================= weight pre-split ==========================================
__global__ void prep_w(const float* __restrict__ W, int k2tot, int n,
                       uint32_t* __restrict__ H, uint32_t* __restrict__ L)
{
    int idx = blockIdx.x * blockDim.x + threadIdx.x;
    if (idx >= k2tot * n) return;
    int k2 = idx / n, nn = idx - k2 * n;
    float v0 = W[(size_t)(2 * k2)     * n + nn];
    float v1 = W[(size_t)(2 * k2 + 1) * n + nn];
    bfsplit2(v0, v1, H[idx], L[idx]);
}

// ================= CSR build =================================================
__global__ void hist_k(const int* __restrict__ ei, int* __restrict__ deg)
{
    int e = blockIdx.x * blockDim.x + threadIdx.x;
    if (e < EE) atomicAdd(&deg[ei[EE + e]], 1);
}

__global__ void scan_k(const int* __restrict__ deg, int* __restrict__ off,
                       int* __restrict__ cur)
{
    __shared__ int wsum[32];
    __shared__ int carry;
    int tid = threadIdx.x, lane = tid & 31, w = tid >> 5;
    if (tid == 0) { carry = 0; off[0] = 0; }
    __syncthreads();
    for (int base = 0; base < NN; base += 1024) {
        int i = base + tid;
        int v = (i < NN) ? deg[i] : 0;
        int s = v;
#pragma unroll
        for (int o = 1; o < 32; o <<= 1) {
            int t = __shfl_up_sync(0xffffffffu, s, o);
            if (lane >= o) s += t;
        }
        if (lane == 31) wsum[w] = s;
        __syncthreads();
        if (w == 0) {
            int ws = wsum[lane];
#pragma unroll
            for (int o = 1; o < 32; o <<= 1) {
                int t = __shfl_up_sync(0xffffffffu, ws, o);
                if (lane >= o) ws += t;
            }
            wsum[lane] = ws;
        }
        __syncthreads();
        int inc = s + (w > 0 ? wsum[w - 1] : 0) + carry;
        if (i < NN) { off[i + 1] = inc; cur[i] = inc - v; }
        int tot = wsum[31];
        __syncthreads();
        if (tid == 0) carry += tot;
        __syncthreads();
    }
}

__global__ void fill_k(const int* __restrict__ ei, int* __restrict__ cur,
                       int* __restrict__ col)
{
    int e = blockIdx.x * blockDim.x + threadIdx.x;
    if (e < EE) {
        int p = atomicAdd(&cur[ei[EE + e]], 1);
        col[p] = ei[e];
    }
}

// ===== CSR gather aggregation: emits split (x + sum_neighbors x) =============
template<int F>
__global__ __launch_bounds__(256)
void csr_agg(const float* __restrict__ x, int ldx,
             const int* __restrict__ off, const int* __restrict__ col,
             uint32_t* __restrict__ aggH, uint32_t* __restrict__ aggL)
{
    int warp = (blockIdx.x * blockDim.x + threadIdx.x) >> 5;
    int lane = threadIdx.x & 31;
    if (warp >= NN) return;
    int o0 = off[warp], o1 = off[warp + 1];
    const int ldw = F / 2;
    if (F == 128) {
        float4 a = ((const float4*)(x + (size_t)warp * ldx))[lane];
        int j = o0;
        for (; j + 1 < o1; j += 2) {
            const float4* r0 = (const float4*)(x + (size_t)col[j]     * ldx);
            const float4* r1 = (const float4*)(x + (size_t)col[j + 1] * ldx);
            float4 v0 = r0[lane], v1 = r1[lane];
            a.x += v0.x + v1.x; a.y += v0.y + v1.y;
            a.z += v0.z + v1.z; a.w += v0.w + v1.w;
        }
        if (j < o1) {
            float4 v = ((const float4*)(x + (size_t)col[j] * ldx))[lane];
            a.x += v.x; a.y += v.y; a.z += v.z; a.w += v.w;
        }
        uint32_t h0, l0, h1, l1;
        bfsplit2(a.x, a.y, h0, l0);
        bfsplit2(a.z, a.w, h1, l1);
        *(uint2*)&aggH[(size_t)warp * ldw + lane * 2] = make_uint2(h0, h1);
        *(uint2*)&aggL[(size_t)warp * ldw + lane * 2] = make_uint2(l0, l1);
    } else {
        const float4* xr = (const float4*)(x + (size_t)warp * ldx);
        float4 a0 = xr[lane], a1 = xr[lane + 32];
        for (int j = o0; j < o1; j++) {
            const float4* r = (const float4*)(x + (size_t)col[j] * ldx);
            float4 v0 = r[lane], v1 = r[lane + 32];
            a0.x += v0.x; a0.y += v0.y; a0.z += v0.z; a0.w += v0.w;
            a1.x += v1.x; a1.y += v1.y; a1.z += v1.z; a1.w += v1.w;
        }
        uint32_t h0, l0, h1, l1;
        bfsplit2(a0.x, a0.y, h0, l0);
        bfsplit2(a0.z, a0.w, h1, l1);
        *(uint2*)&aggH[(size_t)warp * ldw + lane * 2] = make_uint2(h0, h1);
        *(uint2*)&aggL[(size_t)warp * ldw + lane * 2] = make_uint2(l0, l1);
        bfsplit2(a1.x, a1.y, h0, l0);
        bfsplit2(a1.z, a1.w, h1, l1);
        *(uint2*)&aggH[(size_t)warp * ldw + 64 + lane * 2] = make_uint2(h0, h1);
        *(uint2*)&aggL[(size_t)warp * ldw + 64 + lane * 2] = make_uint2(l0, l1);
    }
}

// ================= bf16x3 tensor-core GEMM (pure load/MMA mainloop) =========
__device__ __forceinline__ void mma16(float* c, const uint32_t* a, const uint32_t* b)
{
    asm volatile("mma.sync.aligned.m16n8k16.row.col.f32.bf16.bf16.f32 "
                 "{%0,%1,%2,%3}, {%4,%5,%6,%7}, {%8,%9}, {%0,%1,%2,%3};"
                 : "+f"(c[0]), "+f"(c[1]), "+f"(c[2]), "+f"(c[3])
                 : "r"(a[0]), "r"(a[1]), "r"(a[2]), "r"(a[3]),
                   "r"(b[0]), "r"(b[1]));
}

#define BM 128
#define BN 128
#define LDA_W 12
#define LDB_W 136

// RELU: relu epilogue. OUTMODE: 0 = fp32 only, 1 = fp32 + split Hi/Lo words
template<int RELU, int OUTMODE>
__global__ __launch_bounds__(256, 2)
void gemm_tc(const uint32_t* __restrict__ AH, const uint32_t* __restrict__ AL,
             int ldaW,
             const uint32_t* __restrict__ BH, const uint32_t* __restrict__ BL,
             int Nc,
             const float* __restrict__ bias,
             float* __restrict__ C, int ldc,
             uint32_t* __restrict__ OH, uint32_t* __restrict__ OL,
             int ldoW, int colbase,
             int M, int Kwords)
{
    __shared__ __align__(16) uint32_t AsH[2][BM * LDA_W];
    __shared__ __align__(16) uint32_t AsL[2][BM * LDA_W];
    __shared__ __align__(16) uint32_t BsH[2][8 * LDB_W];
    __shared__ __align__(16) uint32_t BsL[2][8 * LDB_W];

    const int tid  = threadIdx.x;
    const int lane = tid & 31;
    const int wid  = tid >> 5;
    const int gid  = lane >> 2, tig = lane & 3;
    const int wm = (wid & 1) * 64;
    const int wn = (wid >> 1) * 32;
    const int m0 = blockIdx.y * BM;
    const int n0 = blockIdx.x * BN;

    const int am = tid >> 1;
    const int aw = (tid & 1) * 4;
    const int garow = min(m0 + am, M - 1);
    const uint32_t* ArowH = AH + (size_t)garow * ldaW + aw;
    const uint32_t* ArowL = AL + (size_t)garow * ldaW + aw;
    const uint32_t* BrowH = BH + (size_t)wid * Nc + n0 + lane * 4;
    const uint32_t* BrowL = BL + (size_t)wid * Nc + n0 + lane * 4;

    float acc[4][4][4];
#pragma unroll
    for (int i = 0; i < 4; i++)
#pragma unroll
        for (int j = 0; j < 4; j++)
#pragma unroll
            for (int k = 0; k < 4; k++) acc[i][j][k] = 0.f;

    uint4 pAH, pAL, pBH, pBL;
    auto loadG = [&](int k2) {
        pAH = *(const uint4*)(ArowH + k2);
        pAL = *(const uint4*)(ArowL + k2);
        pBH = *(const uint4*)(BrowH + (size_t)k2 * Nc);
        pBL = *(const uint4*)(BrowL + (size_t)k2 * Nc);
    };
    auto storeS = [&](int st) {
        *(uint4*)&AsH[st][am * LDA_W + aw]        = pAH;
        *(uint4*)&AsL[st][am * LDA_W + aw]        = pAL;
        *(uint4*)&BsH[st][wid * LDB_W + lane * 4] = pBH;
        *(uint4*)&BsL[st][wid * LDB_W + lane * 4] = pBL;
    };
    auto compute = [&](int st) {
        uint32_t bH[4][2], bL[4][2];
#pragma unroll
        for (int nt = 0; nt < 4; nt++) {
            int n = wn + nt * 8 + gid;
            bH[nt][0] = BsH[st][ tig      * LDB_W + n];
            bH[nt][1] = BsH[st][(tig + 4) * LDB_W + n];
            bL[nt][0] = BsL[st][ tig      * LDB_W + n];
            bL[nt][1] = BsL[st][(tig + 4) * LDB_W + n];
        }
#pragma unroll
        for (int mt = 0; mt < 4; mt++) {
            int r0 = (wm + mt * 16 + gid) * LDA_W;
            int r8 = r0 + 8 * LDA_W;
            uint32_t aH[4], aL[4];
            aH[0] = AsH[st][r0 + tig];
            aH[1] = AsH[st][r8 + tig];
            aH[2] = AsH[st][r0 + tig + 4];
            aH[3] = AsH[st][r8 + tig + 4];
            aL[0] = AsL[st][r0 + tig];
            aL[1] = AsL[st][r8 + tig];
            aL[2] = AsL[st][r0 + tig + 4];
            aL[3] = AsL[st][r8 + tig + 4];
#pragma unroll
            for (int nt = 0; nt < 4; nt++) {
                mma16(acc[mt][nt], aL, bH[nt]);
                mma16(acc[mt][nt], aH, bL[nt]);
                mma16(acc[mt][nt], aH, bH[nt]);
            }
        }
    };

    loadG(0);
    storeS(0);
    __syncthreads();
    int st = 0;
    for (int k2 = 0; k2 < Kwords; k2 += 8) {
        bool has = (k2 + 8) < Kwords;
        if (has) loadG(k2 + 8);
        compute(st);
        if (has) storeS(st ^ 1);
        __syncthreads();
        st ^= 1;
    }

    // epilogue
#pragma unroll
    for (int nt = 0; nt < 4; nt++) {
        int cn = n0 + wn + nt * 8 + tig * 2;
        float b0 = bias[cn], b1 = bias[cn + 1];
#pragma unroll
        for (int half = 0; half < 2; half++) {
#pragma unroll
            for (int mt = 0; mt < 4; mt++) {
                int r = m0 + wm + mt * 16 + gid + half * 8;
                if (r >= M) continue;
                const float* c = acc[mt][nt];
                float v0 = c[half * 2 + 0] + b0;
                float v1 = c[half * 2 + 1] + b1;
                if (RELU) { v0 = fmaxf(v0, 0.f); v1 = fmaxf(v1, 0.f); }
                *(float2*)&C[(size_t)r * ldc + cn] = make_float2(v0, v1);
                if (OUTMODE == 1) {
                    uint32_t hw, lw;
                    bfsplit2(v0, v1, hw, lw);
                    size_t w = (size_t)r * ldoW + ((colbase + cn) >> 1);
                    OH[w] = hw;
                    OL[w] = lw;
                }
            }
        }
    }
}

// ================= BN stats + transform ======================================
__global__ void stats_kernel(const float* __restrict__ h, int M,
                             float* __restrict__ sum, float* __restrict__ sumsq)
{
    int col = threadIdx.x;
    int r0 = blockIdx.x * 128;
    int r1 = min(r0 + 128, M);
    float s = 0.f, s2 = 0.f;
    for (int r = r0; r < r1; r++) {
        float v = h[(size_t)r * HH + col];
        s  += v;
        s2 += v * v;
    }
    atomicAdd(&sum[col], s);
    atomicAdd(&sumsq[col], s2);
}

__global__ void bnfin_kernel(const float* __restrict__ g, const float* __restrict__ be,
                             const float* __restrict__ sum, const float* __restrict__ sumsq,
                             float* __restrict__ scale, float* __restrict__ shift)
{
    int c = threadIdx.x;
    const float invN = 1.f / (float)NN;
    float mu  = sum[c] * invN;
    float var = fmaxf(sumsq[c] * invN - mu * mu, 0.f);
    float sc  = g[c] * rsqrtf(var + 1e-5f);
    scale[c] = sc;
    shift[c] = be[c] - mu * sc;
}

// relu(h*scale+shift) -> split Hi/Lo packed words (ld = 128 words)
__global__ void bnapply_k(const float* __restrict__ h,
                          const float* __restrict__ scale,
                          const float* __restrict__ shift,
                          uint32_t* __restrict__ H, uint32_t* __restrict__ L)
{
    int idx = blockIdx.x * blockDim.x + threadIdx.x;
    if (idx >= NN * 128) return;
    int m = idx >> 7, j = idx & 127;
    int k = j * 2;
    float2 v = *(const float2*)(h + (size_t)m * HH + k);
    float v0 = fmaxf(fmaf(v.x, scale[k],     shift[k]),     0.f);
    float v1 = fmaxf(fmaf(v.y, scale[k + 1], shift[k + 1]), 0.f);
    bfsplit2(v0, v1, H[idx], L[idx]);
}

// ================= lin2 + softmax head ======================================
__global__ __launch_bounds__(256)
void head_kernel(const float* __restrict__ mid, const float* __restrict__ W,
                 const float* __restrict__ b, float* __restrict__ out,
                 int M, int half)
{
    __shared__ float ws[H3 * 2];
    for (int i = threadIdx.x; i < H3 * 2; i += blockDim.x) ws[i] = W[i];
    __syncthreads();

    int warp = (blockIdx.x * blockDim.x + threadIdx.x) >> 5;
    int lane = threadIdx.x & 31;
    if (warp >= M) return;

    const float* r = mid + (size_t)warp * H3;
    float a0 = 0.f, a1 = 0.f;
    for (int k = lane; k < H3; k += 32) {
        float v = r[k];
        a0 = fmaf(v, ws[2 * k + 0], a0);
        a1 = fmaf(v, ws[2 * k + 1], a1);
    }
#pragma unroll
    for (int o = 16; o; o >>= 1) {
        a0 += __shfl_down_sync(0xffffffffu, a0, o);
        a1 += __shfl_down_sync(0xffffffffu, a1, o);
    }
    if (lane == 0) {
        a0 += b[0];
        a1 += b[1];
        out[warp * 2 + 0] = a0;
        out[warp * 2 + 1] = a1;
        float m  = fmaxf(a0, a1);
        float e0 = expf(a0 - m);
        float e1 = expf(a1 - m);
        float inv = 1.f / (e0 + e1);
        out[half + warp * 2 + 0] = e0 * inv;
        out[half + warp * 2 + 1] = e1 * inv;
    }
}

// ================= host orchestration =======================================
struct Ptrs {
    float *h, *cat, *mid, *sum, *sumsq, *scale, *shift;
    uint32_t *aggH, *aggL, *hH, *hL, *catH, *catL, *WH, *WL;
    int *deg, *off, *cur, *col;
};

static void run_layer(const float* xin, int ldx, int Fin,
                      const Ptrs& P, int w1off, int w2off,
                      const float* b1, const float* gg, const float* be,
                      const float* b2, int catcol)
{
    int aggBlocks = (NN + 7) / 8;
    if (Fin == 128)
        csr_agg<128><<<aggBlocks, 256>>>(xin, ldx, P.off, P.col, P.aggH, P.aggL);
    else
        csr_agg<256><<<aggBlocks, 256>>>(xin, ldx, P.off, P.col, P.aggH, P.aggL);

    dim3 g1(HH / BN, (NN + BM - 1) / BM);
    gemm_tc<0, 0><<<g1, 256>>>(P.aggH, P.aggL, Fin / 2,
                               P.WH + w1off, P.WL + w1off, HH, b1,
                               P.h, HH, nullptr, nullptr, 0, 0, NN, Fin / 2);

    cudaMemsetAsync(P.sum,   0, HH * sizeof(float), 0);
    cudaMemsetAsync(P.sumsq, 0, HH * sizeof(float), 0);
    stats_kernel<<<(NN + 127) / 128, HH>>>(P.h, NN, P.sum, P.sumsq);
    bnfin_kernel<<<1, HH>>>(gg, be, P.sum, P.sumsq, P.scale, P.shift);
    bnapply_k<<<(NN * 128 + 255) / 256, 256>>>(P.h, P.scale, P.shift, P.hH, P.hL);

    // GEMM2: h_l = relu(bn_h @ W2 + b2) -> fp32 cat (for next agg) + split cat
    gemm_tc<1, 1><<<g1, 256>>>(P.hH, P.hL, 128,
                               P.WH + w2off, P.WL + w2off, HH, b2,
                               P.cat + catcol, H3,
                               P.catH, P.catL, 384, catcol, NN, 128);
}

extern "C" void kernel_launch(void* const* d_in, const int* in_sizes, int n_in,
                              void* d_out, int out_size)
{
    const float* x  = (const float*)d_in[0];
    const int*   ei = (const int*)d_in[1];

    const float* c1_W1 = (const float*)d_in[2];
    const float* c1_b1 = (const float*)d_in[3];
    const float* c1_g  = (const float*)d_in[4];
    const float* c1_be = (const float*)d_in[5];
    const float* c1_W2 = (const float*)d_in[6];
    const float* c1_b2 = (const float*)d_in[7];

    const float* c2_W1 = (const float*)d_in[8];
    const float* c2_b1 = (const float*)d_in[9];
    const float* c2_g  = (const float*)d_in[10];
    const float* c2_be = (const float*)d_in[11];
    const float* c2_W2 = (const float*)d_in[12];
    const float* c2_b2 = (const float*)d_in[13];

    const float* c3_W1 = (const float*)d_in[14];
    const float* c3_b1 = (const float*)d_in[15];
    const float* c3_g  = (const float*)d_in[16];
    const float* c3_be = (const float*)d_in[17];
    const float* c3_W2 = (const float*)d_in[18];
    const float* c3_b2 = (const float*)d_in[19];

    const float* lin1_W = (const float*)d_in[20];
    const float* lin1_b = (const float*)d_in[21];
    const float* lin2_W = (const float*)d_in[22];
    const float* lin2_b = (const float*)d_in[23];

    Ptrs P;
    cudaGetSymbolAddress((void**)&P.h,     g_h);
    cudaGetSymbolAddress((void**)&P.cat,   g_cat);
    cudaGetSymbolAddress((void**)&P.mid,   g_mid);
    cudaGetSymbolAddress((void**)&P.sum,   g_sum);
    cudaGetSymbolAddress((void**)&P.sumsq, g_sumsq);
    cudaGetSymbolAddress((void**)&P.scale, g_scale);
    cudaGetSymbolAddress((void**)&P.shift, g_shift);
    cudaGetSymbolAddress((void**)&P.aggH,  g_aggH);
    cudaGetSymbolAddress((void**)&P.aggL,  g_aggL);
    cudaGetSymbolAddress((void**)&P.hH,    g_hH);
    cudaGetSymbolAddress((void**)&P.hL,    g_hL);
    cudaGetSymbolAddress((void**)&P.catH,  g_catH);
    cudaGetSymbolAddress((void**)&P.catL,  g_catL);
    cudaGetSymbolAddress((void**)&P.WH,    g_WH);
    cudaGetSymbolAddress((void**)&P.WL,    g_WL);
    cudaGetSymbolAddress((void**)&P.deg,   g_deg);
    cudaGetSymbolAddress((void**)&P.off,   g_off);
    cudaGetSymbolAddress((void**)&P.cur,   g_cur);
    cudaGetSymbolAddress((void**)&P.col,   g_col);

    auto prep = [&](const float* W, int k, int n, int off) {
        int words = (k / 2) * n;
        prep_w<<<(words + 255) / 256, 256>>>(W, k / 2, n, P.WH + off, P.WL + off);
    };
    prep(c1_W1, INF, HH, W_C1W1);
    prep(c1_W2, HH,  HH, W_C1W2);
    prep(c2_W1, HH,  HH, W_C2W1);
    prep(c2_W2, HH,  HH, W_C2W2);
    prep(c3_W1, HH,  HH, W_C3W1);
    prep(c3_W2, HH,  HH, W_C3W2);
    prep(lin1_W, H3, H3, W_LIN1);

    cudaMemsetAsync(P.deg, 0, NN * sizeof(int), 0);
    hist_k<<<(EE + 255) / 256, 256>>>(ei, P.deg);
    scan_k<<<1, 1024>>>(P.deg, P.off, P.cur);
    fill_k<<<(EE + 255) / 256, 256>>>(ei, P.cur, P.col);

    run_layer(x, INF, INF, P, W_C1W1, W_C1W2, c1_b1, c1_g, c1_be, c1_b2, 0);
    run_layer(P.cat + 0, H3, HH, P, W_C2W1, W_C2W2, c2_b1, c2_g, c2_be, c2_b2, HH);
    run_layer(P.cat + HH, H3, HH, P, W_C3W1, W_C3W2, c3_b1, c3_g, c3_be, c3_b2, 2 * HH);

    dim3 gridL(H3 / BN, (NN + BM - 1) / BM);
    gemm_tc<1, 0><<<gridL, 256>>>(P.catH, P.catL, 384,
                                  P.WH + W_LIN1, P.WL + W_LIN1, H3, lin1_b,
                                  P.mid, H3, nullptr, nullptr, 0, 0, NN, 384);

    int half = out_size / 2;
    float* out = (float*)d_out;
    head_kernel<<<(NN * 32 + 255) / 256, 256>>>(P.mid, lin2_W, lin2_b, out, NN, half);
}

// round 9
// speedup vs baseline: 3.0735x; 1.0227x over previous
#include <cuda_runtime.h>
#include <cuda_bf16.h>
#include <cstdint>

#define NN   50000
#define EE   800000
#define INF  128
#define HH   256
#define H3   768

// ---------------- scratch (static device globals; no allocations) ----------
__device__ float    g_h    [(size_t)NN * HH];          // pre-BN hidden (fp32)
__device__ uint32_t g_aggH [(size_t)NN * 128];         // split (x+agg) packed k-pairs
__device__ uint32_t g_aggL [(size_t)NN * 128];
__device__ uint32_t g_hH   [(size_t)NN * 128];         // split relu(bn(h))
__device__ uint32_t g_hL   [(size_t)NN * 128];
__device__ uint32_t g_catH [(size_t)NN * 384];         // split concat(h1,h2,h3)
__device__ uint32_t g_catL [(size_t)NN * 384];
__device__ uint32_t g_WH   [475136];                   // split weights [K/2][N]
__device__ uint32_t g_WL   [475136];
__device__ float    g_sum  [HH];
__device__ float    g_sumsq[HH];
__device__ float    g_scale[HH];
__device__ float    g_shift[HH];
__device__ int      g_deg  [NN];
__device__ int      g_off  [NN + 1];
__device__ int      g_cur  [NN];
__device__ int      g_col  [EE];

#define W_C1W1 0
#define W_C1W2 16384
#define W_C2W1 49152
#define W_C2W2 81920
#define W_C3W1 114688
#define W_C3W2 147456
#define W_LIN1 180224

// ---------------- bf16 split helpers ----------------------------------------
__device__ __forceinline__ uint32_t pk2(__nv_bfloat16 lo, __nv_bfloat16 hi)
{
    __nv_bfloat162 t; t.x = lo; t.y = hi;
    return *reinterpret_cast<uint32_t*>(&t);
}
__device__ __forceinline__ void bfsplit2(float v0, float v1,
                                         uint32_t& hw, uint32_t& lw)
{
    __nv_bfloat16 h0 = __float2bfloat16(v0);
    __nv_bfloat16 h1 = __float2bfloat16(v1);
    float l0 = v0 - __bfloat162float(h0);
    float l1 = v1 - __bfloat162float(h1);
    hw = pk2(h0, h1);
    lw = pk2(__float2bfloat16(l0), __float2bfloat16(l1));
}
__device__ __forceinline__ float2 up2(uint32_t w)
{
    __nv_bfloat162 t = *reinterpret_cast<__nv_bfloat162*>(&w);
    return make_float2(__bfloat162float(t.x), __bfloat162float(t.y));
}

// ---------------- cp.async helpers -------------------------------------------
#define CP16(dst, src) \
    asm volatile("cp.async.ca.shared.global [%0], [%1], 16;" :: "r"(dst), "l"(src) : "memory")
#define CP_COMMIT() asm volatile("cp.async.commit_group;" ::: "memory")
#define CP_WAIT0()  asm volatile("cp.async.wait_group 0;"  ::: "memory")

__device__ __forceinline__ uint32_t s2u(const void* p)
{
    return (uint32_t)__cvta_generic_to_shared(p);
}

// ================= weight pre-split ([K/2 rows][N cols]) =====================
__global__ void prep_w(const float* __restrict__ W, int k2tot, int n,
                       uint32_t* __restrict__ H, uint32_t* __restrict__ L)
{
    int idx = blockIdx.x * blockDim.x + threadIdx.x;
    if (idx >= k2tot * n) return;
    int k2 = idx / n, nn = idx - k2 * n;
    float v0 = W[(size_t)(2 * k2)     * n + nn];
    float v1 = W[(size_t)(2 * k2 + 1) * n + nn];
    bfsplit2(v0, v1, H[idx], L[idx]);
}

// ================= CSR build =================================================
__global__ void hist_k(const int* __restrict__ ei, int* __restrict__ deg)
{
    int e = blockIdx.x * blockDim.x + threadIdx.x;
    if (e < EE) atomicAdd(&deg[ei[EE + e]], 1);
}

__global__ void scan_k(const int* __restrict__ deg, int* __restrict__ off,
                       int* __restrict__ cur)
{
    __shared__ int wsum[32];
    __shared__ int carry;
    int tid = threadIdx.x, lane = tid & 31, w = tid >> 5;
    if (tid == 0) { carry = 0; off[0] = 0; }
    __syncthreads();
    for (int base = 0; base < NN; base += 1024) {
        int i = base + tid;
        int v = (i < NN) ? deg[i] : 0;
        int s = v;
#pragma unroll
        for (int o = 1; o < 32; o <<= 1) {
            int t = __shfl_up_sync(0xffffffffu, s, o);
            if (lane >= o) s += t;
        }
        if (lane == 31) wsum[w] = s;
        __syncthreads();
        if (w == 0) {
            int ws = wsum[lane];
#pragma unroll
            for (int o = 1; o < 32; o <<= 1) {
                int t = __shfl_up_sync(0xffffffffu, ws, o);
                if (lane >= o) ws += t;
            }
            wsum[lane] = ws;
        }
        __syncthreads();
        int inc = s + (w > 0 ? wsum[w - 1] : 0) + carry;
        if (i < NN) { off[i + 1] = inc; cur[i] = inc - v; }
        int tot = wsum[31];
        __syncthreads();
        if (tid == 0) carry += tot;
        __syncthreads();
    }
}

__global__ void fill_k(const int* __restrict__ ei, int* __restrict__ cur,
                       int* __restrict__ col)
{
    int e = blockIdx.x * blockDim.x + threadIdx.x;
    if (e < EE) {
        int p = atomicAdd(&cur[ei[EE + e]], 1);
        col[p] = ei[e];
    }
}

// ===== layer-1 aggregation from fp32 x: split(x + sum_neighbors x) ==========
__global__ __launch_bounds__(256)
void csr_agg1(const float* __restrict__ x,
              const int* __restrict__ off, const int* __restrict__ col,
              uint32_t* __restrict__ aggH, uint32_t* __restrict__ aggL)
{
    int warp = (blockIdx.x * blockDim.x + threadIdx.x) >> 5;
    int lane = threadIdx.x & 31;
    if (warp >= NN) return;
    int o0 = off[warp], o1 = off[warp + 1];
    float4 a = ((const float4*)(x + (size_t)warp * INF))[lane];
    int j = o0;
    for (; j + 1 < o1; j += 2) {
        const float4* r0 = (const float4*)(x + (size_t)col[j]     * INF);
        const float4* r1 = (const float4*)(x + (size_t)col[j + 1] * INF);
        float4 v0 = r0[lane], v1 = r1[lane];
        a.x += v0.x + v1.x; a.y += v0.y + v1.y;
        a.z += v0.z + v1.z; a.w += v0.w + v1.w;
    }
    if (j < o1) {
        float4 v = ((const float4*)(x + (size_t)col[j] * INF))[lane];
        a.x += v.x; a.y += v.y; a.z += v.z; a.w += v.w;
    }
    uint32_t h0, l0, h1, l1;
    bfsplit2(a.x, a.y, h0, l0);
    bfsplit2(a.z, a.w, h1, l1);
    *(uint2*)&aggH[(size_t)warp * 64 + lane * 2] = make_uint2(h0, h1);
    *(uint2*)&aggL[(size_t)warp * 64 + lane * 2] = make_uint2(l0, l1);
}

// ===== layers 2/3 aggregation from split cat (hi+lo reconstruct) =============
__global__ __launch_bounds__(256)
void csr_agg_sp(const uint32_t* __restrict__ H, const uint32_t* __restrict__ L,
                int woff,
                const int* __restrict__ off, const int* __restrict__ col,
                uint32_t* __restrict__ aggH, uint32_t* __restrict__ aggL)
{
    int warp = (blockIdx.x * blockDim.x + threadIdx.x) >> 5;
    int lane = threadIdx.x & 31;
    if (warp >= NN) return;
    int o0 = off[warp], o1 = off[warp + 1];

    float a[8];
    {
        size_t b = (size_t)warp * 384 + woff + lane * 4;
        uint4 hw = *(const uint4*)(H + b);
        uint4 lw = *(const uint4*)(L + b);
        float2 h, l;
        h = up2(hw.x); l = up2(lw.x); a[0] = h.x + l.x; a[1] = h.y + l.y;
        h = up2(hw.y); l = up2(lw.y); a[2] = h.x + l.x; a[3] = h.y + l.y;
        h = up2(hw.z); l = up2(lw.z); a[4] = h.x + l.x; a[5] = h.y + l.y;
        h = up2(hw.w); l = up2(lw.w); a[6] = h.x + l.x; a[7] = h.y + l.y;
    }
    for (int j = o0; j < o1; j++) {
        size_t b = (size_t)col[j] * 384 + woff + lane * 4;
        uint4 hw = *(const uint4*)(H + b);
        uint4 lw = *(const uint4*)(L + b);
        float2 h, l;
        h = up2(hw.x); l = up2(lw.x); a[0] += h.x + l.x; a[1] += h.y + l.y;
        h = up2(hw.y); l = up2(lw.y); a[2] += h.x + l.x; a[3] += h.y + l.y;
        h = up2(hw.z); l = up2(lw.z); a[4] += h.x + l.x; a[5] += h.y + l.y;
        h = up2(hw.w); l = up2(lw.w); a[6] += h.x + l.x; a[7] += h.y + l.y;
    }
    uint4 oh, ol;
    bfsplit2(a[0], a[1], oh.x, ol.x);
    bfsplit2(a[2], a[3], oh.y, ol.y);
    bfsplit2(a[4], a[5], oh.z, ol.z);
    bfsplit2(a[6], a[7], oh.w, ol.w);
    *(uint4*)&aggH[(size_t)warp * 128 + lane * 4] = oh;
    *(uint4*)&aggL[(size_t)warp * 128 + lane * 4] = ol;
}

// ================= bf16x3 mma.sync GEMM with cp.async pipeline ===============
__device__ __forceinline__ void mma16(float* c, const uint32_t* a, const uint32_t* b)
{
    asm volatile("mma.sync.aligned.m16n8k16.row.col.f32.bf16.bf16.f32 "
                 "{%0,%1,%2,%3}, {%4,%5,%6,%7}, {%8,%9}, {%0,%1,%2,%3};"
                 : "+f"(c[0]), "+f"(c[1]), "+f"(c[2]), "+f"(c[3])
                 : "r"(a[0]), "r"(a[1]), "r"(a[2]), "r"(a[3]),
                   "r"(b[0]), "r"(b[1]));
}

#define BM 128
#define BN 128
#define LDA_W 12
#define LDB_W 136

// MODE: 0 = fp32 C out; 1 = split Hi/Lo out; 2 = fused lin2 head (atomics)
template<int RELU, int MODE>
__global__ __launch_bounds__(256, 2)
void gemm_tc(const uint32_t* __restrict__ AH, const uint32_t* __restrict__ AL,
             int ldaW,
             const uint32_t* __restrict__ BH, const uint32_t* __restrict__ BL,
             int Nc,
             const float* __restrict__ bias,
             float* __restrict__ C, int ldc,
             uint32_t* __restrict__ OH, uint32_t* __restrict__ OL,
             int ldoW, int colbase,
             const float* __restrict__ w2, float* __restrict__ outp,
             int M, int Kw)
{
    __shared__ __align__(16) uint32_t AsH[2][BM * LDA_W];
    __shared__ __align__(16) uint32_t AsL[2][BM * LDA_W];
    __shared__ __align__(16) uint32_t BsH[2][8 * LDB_W];
    __shared__ __align__(16) uint32_t BsL[2][8 * LDB_W];

    const int tid  = threadIdx.x;
    const int lane = tid & 31;
    const int wid  = tid >> 5;
    const int gid  = lane >> 2, tig = lane & 3;
    const int wm = (wid & 1) * 64;
    const int wn = (wid >> 1) * 32;
    const int m0 = blockIdx.y * BM;
    const int n0 = blockIdx.x * BN;

    const int am = tid >> 1;
    const int aw = (tid & 1) * 4;
    const int garow = min(m0 + am, M - 1);
    const uint32_t* ArowH = AH + (size_t)garow * ldaW + aw;
    const uint32_t* ArowL = AL + (size_t)garow * ldaW + aw;
    const uint32_t* BrowH = BH + (size_t)wid * Nc + n0 + lane * 4;
    const uint32_t* BrowL = BL + (size_t)wid * Nc + n0 + lane * 4;

    uint32_t dAH[2], dAL[2], dBH[2], dBL[2];
#pragma unroll
    for (int s = 0; s < 2; s++) {
        dAH[s] = s2u(&AsH[s][am * LDA_W + aw]);
        dAL[s] = s2u(&AsL[s][am * LDA_W + aw]);
        dBH[s] = s2u(&BsH[s][wid * LDB_W + lane * 4]);
        dBL[s] = s2u(&BsL[s][wid * LDB_W + lane * 4]);
    }

    float acc[4][4][4];
#pragma unroll
    for (int i = 0; i < 4; i++)
#pragma unroll
        for (int j = 0; j < 4; j++)
#pragma unroll
            for (int k = 0; k < 4; k++) acc[i][j][k] = 0.f;

    auto issue = [&](int k2, int s) {
        CP16(dAH[s], ArowH + k2);
        CP16(dAL[s], ArowL + k2);
        CP16(dBH[s], BrowH + (size_t)k2 * Nc);
        CP16(dBL[s], BrowL + (size_t)k2 * Nc);
        CP_COMMIT();
    };

    auto compute = [&](int st) {
        uint32_t bH[4][2], bL[4][2];
#pragma unroll
        for (int nt = 0; nt < 4; nt++) {
            int n = wn + nt * 8 + gid;
            bH[nt][0] = BsH[st][ tig      * LDB_W + n];
            bH[nt][1] = BsH[st][(tig + 4) * LDB_W + n];
            bL[nt][0] = BsL[st][ tig      * LDB_W + n];
            bL[nt][1] = BsL[st][(tig + 4) * LDB_W + n];
        }
#pragma unroll
        for (int mt = 0; mt < 4; mt++) {
            int r0 = (wm + mt * 16 + gid) * LDA_W;
            int r8 = r0 + 8 * LDA_W;
            uint32_t aH[4], aL[4];
            aH[0] = AsH[st][r0 + tig];
            aH[1] = AsH[st][r8 + tig];
            aH[2] = AsH[st][r0 + tig + 4];
            aH[3] = AsH[st][r8 + tig + 4];
            aL[0] = AsL[st][r0 + tig];
            aL[1] = AsL[st][r8 + tig];
            aL[2] = AsL[st][r0 + tig + 4];
            aL[3] = AsL[st][r8 + tig + 4];
#pragma unroll
            for (int nt = 0; nt < 4; nt++) {
                mma16(acc[mt][nt], aL, bH[nt]);
                mma16(acc[mt][nt], aH, bL[nt]);
                mma16(acc[mt][nt], aH, bH[nt]);
            }
        }
    };

    const int nt = Kw >> 3;     // stages of 8 k-words
    issue(0, 0);
    int st = 0;
    for (int t = 0; t < nt; t++) {
        CP_WAIT0();
        __syncthreads();
        if (t + 1 < nt) issue((t + 1) * 8, st ^ 1);
        compute(st);
        st ^= 1;
    }

    // ---------------- epilogue ----------------
    if (MODE == 2) {
        float l0a[8] = {0,0,0,0,0,0,0,0};
        float l1a[8] = {0,0,0,0,0,0,0,0};
#pragma unroll
        for (int ntl = 0; ntl < 4; ntl++) {
            int cn = n0 + wn + ntl * 8 + tig * 2;
            float b0 = bias[cn], b1 = bias[cn + 1];
            float w00 = w2[cn * 2],     w01 = w2[cn * 2 + 1];
            float w10 = w2[cn * 2 + 2], w11 = w2[cn * 2 + 3];
#pragma unroll
            for (int half = 0; half < 2; half++) {
#pragma unroll
                for (int mt = 0; mt < 4; mt++) {
                    const float* c = acc[mt][ntl];
                    float v0 = fmaxf(c[half * 2 + 0] + b0, 0.f);
                    float v1 = fmaxf(c[half * 2 + 1] + b1, 0.f);
                    int id = mt * 2 + half;
                    l0a[id] += v0 * w00 + v1 * w10;
                    l1a[id] += v0 * w01 + v1 * w11;
                }
            }
        }
#pragma unroll
        for (int half = 0; half < 2; half++) {
#pragma unroll
            for (int mt = 0; mt < 4; mt++) {
                int id = mt * 2 + half;
                float l0 = l0a[id], l1 = l1a[id];
                l0 += __shfl_xor_sync(0xffffffffu, l0, 1);
                l0 += __shfl_xor_sync(0xffffffffu, l0, 2);
                l1 += __shfl_xor_sync(0xffffffffu, l1, 1);
                l1 += __shfl_xor_sync(0xffffffffu, l1, 2);
                int r = m0 + wm + mt * 16 + gid + half * 8;
                if (tig == 0 && r < M) {
                    atomicAdd(&outp[r * 2],     l0);
                    atomicAdd(&outp[r * 2 + 1], l1);
                }
            }
        }
        return;
    }

#pragma unroll
    for (int ntl = 0; ntl < 4; ntl++) {
        int cn = n0 + wn + ntl * 8 + tig * 2;
        float b0 = bias[cn], b1 = bias[cn + 1];
#pragma unroll
        for (int half = 0; half < 2; half++) {
#pragma unroll
            for (int mt = 0; mt < 4; mt++) {
                int r = m0 + wm + mt * 16 + gid + half * 8;
                if (r >= M) continue;
                const float* c = acc[mt][ntl];
                float v0 = c[half * 2 + 0] + b0;
                float v1 = c[half * 2 + 1] + b1;
                if (RELU) { v0 = fmaxf(v0, 0.f); v1 = fmaxf(v1, 0.f); }
                if (MODE == 0) {
                    *(float2*)&C[(size_t)r * ldc + cn] = make_float2(v0, v1);
                } else {
                    uint32_t hw, lw;
                    bfsplit2(v0, v1, hw, lw);
                    size_t wo = (size_t)r * ldoW + ((colbase + cn) >> 1);
                    OH[wo] = hw;
                    OL[wo] = lw;
                }
            }
        }
    }
}

// ================= BN stats + transform ======================================
__global__ void stats_kernel(const float* __restrict__ h, int M,
                             float* __restrict__ sum, float* __restrict__ sumsq)
{
    int col = threadIdx.x;
    int r0 = blockIdx.x * 128;
    int r1 = min(r0 + 128, M);
    float s = 0.f, s2 = 0.f;
    for (int r = r0; r < r1; r++) {
        float v = h[(size_t)r * HH + col];
        s  += v;
        s2 += v * v;
    }
    atomicAdd(&sum[col], s);
    atomicAdd(&sumsq[col], s2);
}

__global__ void bnfin_kernel(const float* __restrict__ g, const float* __restrict__ be,
                             const float* __restrict__ sum, const float* __restrict__ sumsq,
                             float* __restrict__ scale, float* __restrict__ shift)
{
    int c = threadIdx.x;
    const float invN = 1.f / (float)NN;
    float mu  = sum[c] * invN;
    float var = fmaxf(sumsq[c] * invN - mu * mu, 0.f);
    float sc  = g[c] * rsqrtf(var + 1e-5f);
    scale[c] = sc;
    shift[c] = be[c] - mu * sc;
}

__global__ void bnapply_k(const float* __restrict__ h,
                          const float* __restrict__ scale,
                          const float* __restrict__ shift,
                          uint32_t* __restrict__ H, uint32_t* __restrict__ L)
{
    int idx = blockIdx.x * blockDim.x + threadIdx.x;
    if (idx >= NN * 128) return;
    int m = idx >> 7, j = idx & 127;
    int k = j * 2;
    float2 v = *(const float2*)(h + (size_t)m * HH + k);
    float v0 = fmaxf(fmaf(v.x, scale[k],     shift[k]),     0.f);
    float v1 = fmaxf(fmaf(v.y, scale[k + 1], shift[k + 1]), 0.f);
    bfsplit2(v0, v1, H[idx], L[idx]);
}

// ================= head init + softmax =======================================
__global__ void init_out_k(float* __restrict__ out, const float* __restrict__ b)
{
    int i = blockIdx.x * blockDim.x + threadIdx.x;
    if (i < NN * 2) out[i] = b[i & 1];
}

__global__ void softmax_k(float* __restrict__ out, int half)
{
    int i = blockIdx.x * blockDim.x + threadIdx.x;
    if (i >= NN) return;
    float a0 = out[i * 2], a1 = out[i * 2 + 1];
    float m  = fmaxf(a0, a1);
    float e0 = expf(a0 - m);
    float e1 = expf(a1 - m);
    float inv = 1.f / (e0 + e1);
    out[half + i * 2]     = e0 * inv;
    out[half + i * 2 + 1] = e1 * inv;
}

// ================= host orchestration =======================================
struct Ptrs {
    float *h, *sum, *sumsq, *scale, *shift;
    uint32_t *aggH, *aggL, *hH, *hL, *catH, *catL, *WH, *WL;
    int *deg, *off, *cur, *col;
};

#define MT ((NN + 127) / 128)

static void run_layer(int layer, const Ptrs& P, int w1off, int w2off,
                      const float* xin,
                      const float* b1, const float* gg, const float* be,
                      const float* b2, int catcol)
{
    int aggBlocks = (NN + 7) / 8;
    if (layer == 1)
        csr_agg1<<<aggBlocks, 256>>>(xin, P.off, P.col, P.aggH, P.aggL);
    else
        csr_agg_sp<<<aggBlocks, 256>>>(P.catH, P.catL, (layer - 2) * 128,
                                       P.off, P.col, P.aggH, P.aggL);

    int Kw = (layer == 1) ? 64 : 128;
    dim3 g1(HH / BN, MT);
    gemm_tc<0, 0><<<g1, 256>>>(P.aggH, P.aggL, Kw,
                               P.WH + w1off, P.WL + w1off, HH, b1,
                               P.h, HH, nullptr, nullptr, 0, 0,
                               nullptr, nullptr, NN, Kw);

    cudaMemsetAsync(P.sum,   0, HH * sizeof(float), 0);
    cudaMemsetAsync(P.sumsq, 0, HH * sizeof(float), 0);
    stats_kernel<<<(NN + 127) / 128, HH>>>(P.h, NN, P.sum, P.sumsq);
    bnfin_kernel<<<1, HH>>>(gg, be, P.sum, P.sumsq, P.scale, P.shift);
    bnapply_k<<<(NN * 128 + 255) / 256, 256>>>(P.h, P.scale, P.shift, P.hH, P.hL);

    gemm_tc<1, 1><<<g1, 256>>>(P.hH, P.hL, 128,
                               P.WH + w2off, P.WL + w2off, HH, b2,
                               nullptr, 0, P.catH, P.catL, 384, catcol,
                               nullptr, nullptr, NN, 128);
}

extern "C" void kernel_launch(void* const* d_in, const int* in_sizes, int n_in,
                              void* d_out, int out_size)
{
    const float* x  = (const float*)d_in[0];
    const int*   ei = (const int*)d_in[1];

    const float* c1_W1 = (const float*)d_in[2];
    const float* c1_b1 = (const float*)d_in[3];
    const float* c1_g  = (const float*)d_in[4];
    const float* c1_be = (const float*)d_in[5];
    const float* c1_W2 = (const float*)d_in[6];
    const float* c1_b2 = (const float*)d_in[7];

    const float* c2_W1 = (const float*)d_in[8];
    const float* c2_b1 = (const float*)d_in[9];
    const float* c2_g  = (const float*)d_in[10];
    const float* c2_be = (const float*)d_in[11];
    const float* c2_W2 = (const float*)d_in[12];
    const float* c2_b2 = (const float*)d_in[13];

    const float* c3_W1 = (const float*)d_in[14];
    const float* c3_b1 = (const float*)d_in[15];
    const float* c3_g  = (const float*)d_in[16];
    const float* c3_be = (const float*)d_in[17];
    const float* c3_W2 = (const float*)d_in[18];
    const float* c3_b2 = (const float*)d_in[19];

    const float* lin1_W = (const float*)d_in[20];
    const float* lin1_b = (const float*)d_in[21];
    const float* lin2_W = (const float*)d_in[22];
    const float* lin2_b = (const float*)d_in[23];

    Ptrs P;
    cudaGetSymbolAddress((void**)&P.h,     g_h);
    cudaGetSymbolAddress((void**)&P.sum,   g_sum);
    cudaGetSymbolAddress((void**)&P.sumsq, g_sumsq);
    cudaGetSymbolAddress((void**)&P.scale, g_scale);
    cudaGetSymbolAddress((void**)&P.shift, g_shift);
    cudaGetSymbolAddress((void**)&P.aggH,  g_aggH);
    cudaGetSymbolAddress((void**)&P.aggL,  g_aggL);
    cudaGetSymbolAddress((void**)&P.hH,    g_hH);
    cudaGetSymbolAddress((void**)&P.hL,    g_hL);
    cudaGetSymbolAddress((void**)&P.catH,  g_catH);
    cudaGetSymbolAddress((void**)&P.catL,  g_catL);
    cudaGetSymbolAddress((void**)&P.WH,    g_WH);
    cudaGetSymbolAddress((void**)&P.WL,    g_WL);
    cudaGetSymbolAddress((void**)&P.deg,   g_deg);
    cudaGetSymbolAddress((void**)&P.off,   g_off);
    cudaGetSymbolAddress((void**)&P.cur,   g_cur);
    cudaGetSymbolAddress((void**)&P.col,   g_col);

    auto prep = [&](const float* W, int k, int n, int off) {
        int words = (k / 2) * n;
        prep_w<<<(words + 255) / 256, 256>>>(W, k / 2, n, P.WH + off, P.WL + off);
    };
    prep(c1_W1, INF, HH, W_C1W1);
    prep(c1_W2, HH,  HH, W_C1W2);
    prep(c2_W1, HH,  HH, W_C2W1);
    prep(c2_W2, HH,  HH, W_C2W2);
    prep(c3_W1, HH,  HH, W_C3W1);
    prep(c3_W2, HH,  HH, W_C3W2);
    prep(lin1_W, H3, H3, W_LIN1);

    cudaMemsetAsync(P.deg, 0, NN * sizeof(int), 0);
    hist_k<<<(EE + 255) / 256, 256>>>(ei, P.deg);
    scan_k<<<1, 1024>>>(P.deg, P.off, P.cur);
    fill_k<<<(EE + 255) / 256, 256>>>(ei, P.cur, P.col);

    run_layer(1, P, W_C1W1, W_C1W2, x, c1_b1, c1_g, c1_be, c1_b2, 0);
    run_layer(2, P, W_C2W1, W_C2W2, nullptr, c2_b1, c2_g, c2_be, c2_b2, HH);
    run_layer(3, P, W_C3W1, W_C3W2, nullptr, c3_b1, c3_g, c3_be, c3_b2, 2 * HH);

    // fused readout: lin1 (relu) + lin2 via atomics, then softmax
    float* out = (float*)d_out;
    init_out_k<<<(NN * 2 + 255) / 256, 256>>>(out, lin2_b);

    dim3 gridL(H3 / BN, MT);
    gemm_tc<1, 2><<<gridL, 256>>>(P.catH, P.catL, 384,
                                  P.WH + W_LIN1, P.WL + W_LIN1, H3, lin1_b,
                                  nullptr, 0, nullptr, nullptr, 0, 0,
                                  lin2_W, out, NN, 384);

    int half = out_size / 2;
    softmax_k<<<(NN + 255) / 256, 256>>>(out, half);
}

// round 10
// speedup vs baseline: 3.2357x; 1.0528x over previous
#include <cuda_runtime.h>
#include <cuda_bf16.h>
#include <cstdint>

#define NN   50000
#define EE   800000
#define INF  128
#define HH   256
#define H3   768

// ---------------- scratch (static device globals; no allocations) ----------
__device__ float    g_h    [(size_t)NN * HH];          // pre-BN hidden (fp32)
__device__ uint32_t g_aggH [(size_t)NN * 128];         // split (x+agg) packed k-pairs
__device__ uint32_t g_aggL [(size_t)NN * 128];
__device__ uint32_t g_catH [(size_t)NN * 384];         // split concat(h1,h2,h3)
__device__ uint32_t g_catL [(size_t)NN * 384];
__device__ uint32_t g_WH   [475136];                   // split weights [K/2][N]
__device__ uint32_t g_WL   [475136];
__device__ float    g_sum  [HH];
__device__ float    g_sumsq[HH];
__device__ float    g_scale[HH];
__device__ float    g_shift[HH];
__device__ int      g_deg  [NN];
__device__ int      g_off  [NN + 1];
__device__ int      g_cur  [NN];
__device__ int      g_col  [EE];

#define W_C1W1 0
#define W_C1W2 16384
#define W_C2W1 49152
#define W_C2W2 81920
#define W_C3W1 114688
#define W_C3W2 147456
#define W_LIN1 180224
#define W_TOT  475136

// ---------------- bf16 split helpers ----------------------------------------
__device__ __forceinline__ uint32_t pk2(__nv_bfloat16 lo, __nv_bfloat16 hi)
{
    __nv_bfloat162 t; t.x = lo; t.y = hi;
    return *reinterpret_cast<uint32_t*>(&t);
}
__device__ __forceinline__ void bfsplit2(float v0, float v1,
                                         uint32_t& hw, uint32_t& lw)
{
    __nv_bfloat16 h0 = __float2bfloat16(v0);
    __nv_bfloat16 h1 = __float2bfloat16(v1);
    float l0 = v0 - __bfloat162float(h0);
    float l1 = v1 - __bfloat162float(h1);
    hw = pk2(h0, h1);
    lw = pk2(__float2bfloat16(l0), __float2bfloat16(l1));
}
__device__ __forceinline__ float2 up2(uint32_t w)
{
    __nv_bfloat162 t = *reinterpret_cast<__nv_bfloat162*>(&w);
    return make_float2(__bfloat162float(t.x), __bfloat162float(t.y));
}

// ---------------- cp.async helpers -------------------------------------------
#define CP16(dst, src) \
    asm volatile("cp.async.ca.shared.global [%0], [%1], 16;" :: "r"(dst), "l"(src) : "memory")
#define CP_COMMIT() asm volatile("cp.async.commit_group;" ::: "memory")
#define CP_WAIT0()  asm volatile("cp.async.wait_group 0;"  ::: "memory")

__device__ __forceinline__ uint32_t s2u(const void* p)
{
    return (uint32_t)__cvta_generic_to_shared(p);
}

// ================= consolidated weight pre-split =============================
__global__ void prep_all(const float* __restrict__ w0, const float* __restrict__ w1,
                         const float* __restrict__ w2, const float* __restrict__ w3,
                         const float* __restrict__ w4, const float* __restrict__ w5,
                         const float* __restrict__ w6,
                         uint32_t* __restrict__ H, uint32_t* __restrict__ L)
{
    int idx = blockIdx.x * blockDim.x + threadIdx.x;
    if (idx >= W_TOT) return;
    const float* src;
    int base, n;
    if      (idx < W_C1W2) { src = w0; base = W_C1W1; n = HH; }
    else if (idx < W_C2W1) { src = w1; base = W_C1W2; n = HH; }
    else if (idx < W_C2W2) { src = w2; base = W_C2W1; n = HH; }
    else if (idx < W_C3W1) { src = w3; base = W_C2W2; n = HH; }
    else if (idx < W_C3W2) { src = w4; base = W_C3W1; n = HH; }
    else if (idx < W_LIN1) { src = w5; base = W_C3W2; n = HH; }
    else                   { src = w6; base = W_LIN1; n = H3; }
    int loc = idx - base;
    int k2 = loc / n, nn = loc - k2 * n;
    float v0 = src[(size_t)(2 * k2)     * n + nn];
    float v1 = src[(size_t)(2 * k2 + 1) * n + nn];
    bfsplit2(v0, v1, H[idx], L[idx]);
}

// ================= CSR build =================================================
__global__ void hist_k(const int* __restrict__ ei, int* __restrict__ deg)
{
    int e = blockIdx.x * blockDim.x + threadIdx.x;
    if (e < EE) atomicAdd(&deg[ei[EE + e]], 1);
}

__global__ void scan_k(const int* __restrict__ deg, int* __restrict__ off,
                       int* __restrict__ cur)
{
    __shared__ int wsum[32];
    __shared__ int carry;
    int tid = threadIdx.x, lane = tid & 31, w = tid >> 5;
    if (tid == 0) { carry = 0; off[0] = 0; }
    __syncthreads();
    for (int base = 0; base < NN; base += 1024) {
        int i = base + tid;
        int v = (i < NN) ? deg[i] : 0;
        int s = v;
#pragma unroll
        for (int o = 1; o < 32; o <<= 1) {
            int t = __shfl_up_sync(0xffffffffu, s, o);
            if (lane >= o) s += t;
        }
        if (lane == 31) wsum[w] = s;
        __syncthreads();
        if (w == 0) {
            int ws = wsum[lane];
#pragma unroll
            for (int o = 1; o < 32; o <<= 1) {
                int t = __shfl_up_sync(0xffffffffu, ws, o);
                if (lane >= o) ws += t;
            }
            wsum[lane] = ws;
        }
        __syncthreads();
        int inc = s + (w > 0 ? wsum[w - 1] : 0) + carry;
        if (i < NN) { off[i + 1] = inc; cur[i] = inc - v; }
        int tot = wsum[31];
        __syncthreads();
        if (tid == 0) carry += tot;
        __syncthreads();
    }
}

__global__ void fill_k(const int* __restrict__ ei, int* __restrict__ cur,
                       int* __restrict__ col)
{
    int e = blockIdx.x * blockDim.x + threadIdx.x;
    if (e < EE) {
        int p = atomicAdd(&cur[ei[EE + e]], 1);
        col[p] = ei[e];
    }
}

// ===== layer-1 aggregation from fp32 x: split(x + sum_neighbors x) ==========
__global__ __launch_bounds__(256)
void csr_agg1(const float* __restrict__ x,
              const int* __restrict__ off, const int* __restrict__ col,
              uint32_t* __restrict__ aggH, uint32_t* __restrict__ aggL)
{
    int warp = (blockIdx.x * blockDim.x + threadIdx.x) >> 5;
    int lane = threadIdx.x & 31;
    if (warp >= NN) return;
    int o0 = off[warp], o1 = off[warp + 1];
    float4 a = ((const float4*)(x + (size_t)warp * INF))[lane];
    int j = o0;
    for (; j + 1 < o1; j += 2) {
        const float4* r0 = (const float4*)(x + (size_t)col[j]     * INF);
        const float4* r1 = (const float4*)(x + (size_t)col[j + 1] * INF);
        float4 v0 = r0[lane], v1 = r1[lane];
        a.x += v0.x + v1.x; a.y += v0.y + v1.y;
        a.z += v0.z + v1.z; a.w += v0.w + v1.w;
    }
    if (j < o1) {
        float4 v = ((const float4*)(x + (size_t)col[j] * INF))[lane];
        a.x += v.x; a.y += v.y; a.z += v.z; a.w += v.w;
    }
    uint32_t h0, l0, h1, l1;
    bfsplit2(a.x, a.y, h0, l0);
    bfsplit2(a.z, a.w, h1, l1);
    *(uint2*)&aggH[(size_t)warp * 64 + lane * 2] = make_uint2(h0, h1);
    *(uint2*)&aggL[(size_t)warp * 64 + lane * 2] = make_uint2(l0, l1);
}

// ===== layers 2/3 aggregation from split cat (hi+lo reconstruct) =============
__global__ __launch_bounds__(256)
void csr_agg_sp(const uint32_t* __restrict__ H, const uint32_t* __restrict__ L,
                int woff,
                const int* __restrict__ off, const int* __restrict__ col,
                uint32_t* __restrict__ aggH, uint32_t* __restrict__ aggL)
{
    int warp = (blockIdx.x * blockDim.x + threadIdx.x) >> 5;
    int lane = threadIdx.x & 31;
    if (warp >= NN) return;
    int o0 = off[warp], o1 = off[warp + 1];

    float a[8];
    {
        size_t b = (size_t)warp * 384 + woff + lane * 4;
        uint4 hw = *(const uint4*)(H + b);
        uint4 lw = *(const uint4*)(L + b);
        float2 h, l;
        h = up2(hw.x); l = up2(lw.x); a[0] = h.x + l.x; a[1] = h.y + l.y;
        h = up2(hw.y); l = up2(lw.y); a[2] = h.x + l.x; a[3] = h.y + l.y;
        h = up2(hw.z); l = up2(lw.z); a[4] = h.x + l.x; a[5] = h.y + l.y;
        h = up2(hw.w); l = up2(lw.w); a[6] = h.x + l.x; a[7] = h.y + l.y;
    }
    for (int j = o0; j < o1; j++) {
        size_t b = (size_t)col[j] * 384 + woff + lane * 4;
        uint4 hw = *(const uint4*)(H + b);
        uint4 lw = *(const uint4*)(L + b);
        float2 h, l;
        h = up2(hw.x); l = up2(lw.x); a[0] += h.x + l.x; a[1] += h.y + l.y;
        h = up2(hw.y); l = up2(lw.y); a[2] += h.x + l.x; a[3] += h.y + l.y;
        h = up2(hw.z); l = up2(lw.z); a[4] += h.x + l.x; a[5] += h.y + l.y;
        h = up2(hw.w); l = up2(lw.w); a[6] += h.x + l.x; a[7] += h.y + l.y;
    }
    uint4 oh, ol;
    bfsplit2(a[0], a[1], oh.x, ol.x);
    bfsplit2(a[2], a[3], oh.y, ol.y);
    bfsplit2(a[4], a[5], oh.z, ol.z);
    bfsplit2(a[6], a[7], oh.w, ol.w);
    *(uint4*)&aggH[(size_t)warp * 128 + lane * 4] = oh;
    *(uint4*)&aggL[(size_t)warp * 128 + lane * 4] = ol;
}

// ================= bf16x3 mma.sync GEMM ======================================
__device__ __forceinline__ void mma16(float* c, const uint32_t* a, const uint32_t* b)
{
    asm volatile("mma.sync.aligned.m16n8k16.row.col.f32.bf16.bf16.f32 "
                 "{%0,%1,%2,%3}, {%4,%5,%6,%7}, {%8,%9}, {%0,%1,%2,%3};"
                 : "+f"(c[0]), "+f"(c[1]), "+f"(c[2]), "+f"(c[3])
                 : "r"(a[0]), "r"(a[1]), "r"(a[2]), "r"(a[3]),
                   "r"(b[0]), "r"(b[1]));
}

#define BM 128
#define BN 128
#define LDA_W 12
#define LDB_W 136

// AMODE: 0 = split A via cp.async; 2 = fp32 A + fused BN(relu)+split
// MODE:  0 = fp32 C out; 1 = split Hi/Lo out; 2 = fused lin2 head (atomics)
// STATS: 1 = accumulate column sum/sumsq of (acc+bias) into sumv/sumsqv
template<int AMODE, int RELU, int MODE, int STATS>
__global__ __launch_bounds__(256, 2)
void gemm_tc(const uint32_t* __restrict__ AH, const uint32_t* __restrict__ AL,
             const float* __restrict__ Afp, int ldaW,
             const uint32_t* __restrict__ BH, const uint32_t* __restrict__ BL,
             int Nc,
             const float* __restrict__ bias,
             const float* __restrict__ scale, const float* __restrict__ shift,
             float* __restrict__ C, int ldc,
             uint32_t* __restrict__ OH, uint32_t* __restrict__ OL,
             int ldoW, int colbase,
             const float* __restrict__ w2, float* __restrict__ outp,
             float* __restrict__ sumv, float* __restrict__ sumsqv,
             int M, int Kw)
{
    __shared__ __align__(16) uint32_t AsH[2][BM * LDA_W];
    __shared__ __align__(16) uint32_t AsL[2][BM * LDA_W];
    __shared__ __align__(16) uint32_t BsH[2][8 * LDB_W];
    __shared__ __align__(16) uint32_t BsL[2][8 * LDB_W];

    const int tid  = threadIdx.x;
    const int lane = tid & 31;
    const int wid  = tid >> 5;
    const int gid  = lane >> 2, tig = lane & 3;
    const int wm = (wid & 1) * 64;
    const int wn = (wid >> 1) * 32;
    const int m0 = blockIdx.y * BM;
    const int n0 = blockIdx.x * BN;

    const int am = tid >> 1;
    const int aw = (tid & 1) * 4;
    const int garow = min(m0 + am, M - 1);
    const uint32_t* ArowH = AH + (size_t)garow * ldaW + aw;
    const uint32_t* ArowL = AL + (size_t)garow * ldaW + aw;
    const float*    ArowF = Afp + (size_t)garow * (ldaW * 2) + aw * 2;
    const uint32_t* BrowH = BH + (size_t)wid * Nc + n0 + lane * 4;
    const uint32_t* BrowL = BL + (size_t)wid * Nc + n0 + lane * 4;

    uint32_t dAH[2], dAL[2], dBH[2], dBL[2];
#pragma unroll
    for (int s = 0; s < 2; s++) {
        dAH[s] = s2u(&AsH[s][am * LDA_W + aw]);
        dAL[s] = s2u(&AsL[s][am * LDA_W + aw]);
        dBH[s] = s2u(&BsH[s][wid * LDB_W + lane * 4]);
        dBL[s] = s2u(&BsL[s][wid * LDB_W + lane * 4]);
    }

    float acc[4][4][4];
#pragma unroll
    for (int i = 0; i < 4; i++)
#pragma unroll
        for (int j = 0; j < 4; j++)
#pragma unroll
            for (int k = 0; k < 4; k++) acc[i][j][k] = 0.f;

    float aR[8];

    auto issueB = [&](int k2, int s) {
        CP16(dBH[s], BrowH + (size_t)k2 * Nc);
        CP16(dBL[s], BrowL + (size_t)k2 * Nc);
        CP_COMMIT();
    };
    auto issueA0 = [&](int k2, int s) {
        CP16(dAH[s], ArowH + k2);
        CP16(dAL[s], ArowL + k2);
    };
    auto loadA2 = [&](int k2) {
        const float* p = ArowF + k2 * 2;
        float4 u0 = *(const float4*)(p);
        float4 u1 = *(const float4*)(p + 4);
        aR[0]=u0.x; aR[1]=u0.y; aR[2]=u0.z; aR[3]=u0.w;
        aR[4]=u1.x; aR[5]=u1.y; aR[6]=u1.z; aR[7]=u1.w;
    };
    auto stsA2 = [&](int k2, int s) {
        int ke = k2 * 2 + aw * 2;
        float v[8];
#pragma unroll
        for (int j = 0; j < 8; j++)
            v[j] = fmaxf(fmaf(aR[j], scale[ke + j], shift[ke + j]), 0.f);
        uint4 hv, lv;
        bfsplit2(v[0], v[1], hv.x, lv.x);
        bfsplit2(v[2], v[3], hv.y, lv.y);
        bfsplit2(v[4], v[5], hv.z, lv.z);
        bfsplit2(v[6], v[7], hv.w, lv.w);
        *(uint4*)&AsH[s][am * LDA_W + aw] = hv;
        *(uint4*)&AsL[s][am * LDA_W + aw] = lv;
    };

    auto compute = [&](int st) {
        uint32_t bH[4][2], bL[4][2];
#pragma unroll
        for (int nt = 0; nt < 4; nt++) {
            int n = wn + nt * 8 + gid;
            bH[nt][0] = BsH[st][ tig      * LDB_W + n];
            bH[nt][1] = BsH[st][(tig + 4) * LDB_W + n];
            bL[nt][0] = BsL[st][ tig      * LDB_W + n];
            bL[nt][1] = BsL[st][(tig + 4) * LDB_W + n];
        }
#pragma unroll
        for (int mt = 0; mt < 4; mt++) {
            int r0 = (wm + mt * 16 + gid) * LDA_W;
            int r8 = r0 + 8 * LDA_W;
            uint32_t aHr[4], aLr[4];
            aHr[0] = AsH[st][r0 + tig];
            aHr[1] = AsH[st][r8 + tig];
            aHr[2] = AsH[st][r0 + tig + 4];
            aHr[3] = AsH[st][r8 + tig + 4];
            aLr[0] = AsL[st][r0 + tig];
            aLr[1] = AsL[st][r8 + tig];
            aLr[2] = AsL[st][r0 + tig + 4];
            aLr[3] = AsL[st][r8 + tig + 4];
#pragma unroll
            for (int nt = 0; nt < 4; nt++) {
                mma16(acc[mt][nt], aLr, bH[nt]);
                mma16(acc[mt][nt], aHr, bL[nt]);
                mma16(acc[mt][nt], aHr, bH[nt]);
            }
        }
    };

    const int nt = Kw >> 3;
    // prologue
    if (AMODE == 0) {
        issueA0(0, 0);
        issueB(0, 0);
    } else {
        loadA2(0);
        stsA2(0, 0);
        issueB(0, 0);
    }
    int st = 0;
    for (int t = 0; t < nt; t++) {
        bool has = (t + 1) < nt;
        if (AMODE == 2 && has) loadA2((t + 1) * 8);
        CP_WAIT0();
        __syncthreads();
        if (has) {
            if (AMODE == 0) issueA0((t + 1) * 8, st ^ 1);
            issueB((t + 1) * 8, st ^ 1);
        }
        compute(st);
        if (AMODE == 2 && has) stsA2((t + 1) * 8, st ^ 1);
        st ^= 1;
    }

    // ---------------- epilogue ----------------
    if (MODE == 2) {
        float l0a[8] = {0,0,0,0,0,0,0,0};
        float l1a[8] = {0,0,0,0,0,0,0,0};
#pragma unroll
        for (int ntl = 0; ntl < 4; ntl++) {
            int cn = n0 + wn + ntl * 8 + tig * 2;
            float b0 = bias[cn], b1 = bias[cn + 1];
            float w00 = w2[cn * 2],     w01 = w2[cn * 2 + 1];
            float w10 = w2[cn * 2 + 2], w11 = w2[cn * 2 + 3];
#pragma unroll
            for (int half = 0; half < 2; half++) {
#pragma unroll
                for (int mt = 0; mt < 4; mt++) {
                    const float* c = acc[mt][ntl];
                    float v0 = fmaxf(c[half * 2 + 0] + b0, 0.f);
                    float v1 = fmaxf(c[half * 2 + 1] + b1, 0.f);
                    int id = mt * 2 + half;
                    l0a[id] += v0 * w00 + v1 * w10;
                    l1a[id] += v0 * w01 + v1 * w11;
                }
            }
        }
#pragma unroll
        for (int half = 0; half < 2; half++) {
#pragma unroll
            for (int mt = 0; mt < 4; mt++) {
                int id = mt * 2 + half;
                float l0 = l0a[id], l1 = l1a[id];
                l0 += __shfl_xor_sync(0xffffffffu, l0, 1);
                l0 += __shfl_xor_sync(0xffffffffu, l0, 2);
                l1 += __shfl_xor_sync(0xffffffffu, l1, 1);
                l1 += __shfl_xor_sync(0xffffffffu, l1, 2);
                int r = m0 + wm + mt * 16 + gid + half * 8;
                if (tig == 0 && r < M) {
                    atomicAdd(&outp[r * 2],     l0);
                    atomicAdd(&outp[r * 2 + 1], l1);
                }
            }
        }
        return;
    }

#pragma unroll
    for (int ntl = 0; ntl < 4; ntl++) {
        int cn = n0 + wn + ntl * 8 + tig * 2;
        float b0 = bias[cn], b1 = bias[cn + 1];
        float s0 = 0.f, s1 = 0.f, q0 = 0.f, q1 = 0.f;
#pragma unroll
        for (int half = 0; half < 2; half++) {
#pragma unroll
            for (int mt = 0; mt < 4; mt++) {
                int r = m0 + wm + mt * 16 + gid + half * 8;
                if (r >= M) continue;
                const float* c = acc[mt][ntl];
                float v0 = c[half * 2 + 0] + b0;
                float v1 = c[half * 2 + 1] + b1;
                if (RELU) { v0 = fmaxf(v0, 0.f); v1 = fmaxf(v1, 0.f); }
                if (MODE == 0) {
                    *(float2*)&C[(size_t)r * ldc + cn] = make_float2(v0, v1);
                } else {
                    uint32_t hw, lw;
                    bfsplit2(v0, v1, hw, lw);
                    size_t wo = (size_t)r * ldoW + ((colbase + cn) >> 1);
                    OH[wo] = hw;
                    OL[wo] = lw;
                }
                if (STATS) {
                    s0 += v0; q0 += v0 * v0;
                    s1 += v1; q1 += v1 * v1;
                }
            }
        }
        if (STATS) {
#pragma unroll
            for (int o = 4; o < 32; o <<= 1) {
                s0 += __shfl_xor_sync(0xffffffffu, s0, o);
                s1 += __shfl_xor_sync(0xffffffffu, s1, o);
                q0 += __shfl_xor_sync(0xffffffffu, q0, o);
                q1 += __shfl_xor_sync(0xffffffffu, q1, o);
            }
            if (gid == 0) {
                atomicAdd(&sumv[cn],       s0);
                atomicAdd(&sumv[cn + 1],   s1);
                atomicAdd(&sumsqv[cn],     q0);
                atomicAdd(&sumsqv[cn + 1], q1);
            }
        }
    }
}

// ================= BN finalize ================================================
__global__ void bnfin_kernel(const float* __restrict__ g, const float* __restrict__ be,
                             const float* __restrict__ sum, const float* __restrict__ sumsq,
                             float* __restrict__ scale, float* __restrict__ shift)
{
    int c = threadIdx.x;
    const float invN = 1.f / (float)NN;
    float mu  = sum[c] * invN;
    float var = fmaxf(sumsq[c] * invN - mu * mu, 0.f);
    float sc  = g[c] * rsqrtf(var + 1e-5f);
    scale[c] = sc;
    shift[c] = be[c] - mu * sc;
}

// ================= head init + softmax =======================================
__global__ void init_out_k(float* __restrict__ out, const float* __restrict__ b)
{
    int i = blockIdx.x * blockDim.x + threadIdx.x;
    if (i < NN * 2) out[i] = b[i & 1];
}

__global__ void softmax_k(float* __restrict__ out, int half)
{
    int i = blockIdx.x * blockDim.x + threadIdx.x;
    if (i >= NN) return;
    float a0 = out[i * 2], a1 = out[i * 2 + 1];
    float m  = fmaxf(a0, a1);
    float e0 = expf(a0 - m);
    float e1 = expf(a1 - m);
    float inv = 1.f / (e0 + e1);
    out[half + i * 2]     = e0 * inv;
    out[half + i * 2 + 1] = e1 * inv;
}

// ================= host orchestration =======================================
struct Ptrs {
    float *h, *sum, *sumsq, *scale, *shift;
    uint32_t *aggH, *aggL, *catH, *catL, *WH, *WL;
    int *deg, *off, *cur, *col;
};

#define MT ((NN + 127) / 128)

static void run_layer(int layer, const Ptrs& P, int w1off, int w2off,
                      const float* xin,
                      const float* b1, const float* gg, const float* be,
                      const float* b2, int catcol)
{
    int aggBlocks = (NN + 7) / 8;
    if (layer == 1)
        csr_agg1<<<aggBlocks, 256>>>(xin, P.off, P.col, P.aggH, P.aggL);
    else
        csr_agg_sp<<<aggBlocks, 256>>>(P.catH, P.catL, (layer - 2) * 128,
                                       P.off, P.col, P.aggH, P.aggL);

    cudaMemsetAsync(P.sum,   0, HH * sizeof(float), 0);
    cudaMemsetAsync(P.sumsq, 0, HH * sizeof(float), 0);

    int Kw = (layer == 1) ? 64 : 128;
    dim3 g1(HH / BN, MT);
    // GEMM1 with fused BN stats
    gemm_tc<0, 0, 0, 1><<<g1, 256>>>(P.aggH, P.aggL, nullptr, Kw,
                                     P.WH + w1off, P.WL + w1off, HH, b1,
                                     nullptr, nullptr,
                                     P.h, HH, nullptr, nullptr, 0, 0,
                                     nullptr, nullptr, P.sum, P.sumsq, NN, Kw);

    bnfin_kernel<<<1, HH>>>(gg, be, P.sum, P.sumsq, P.scale, P.shift);

    // GEMM2 with fused BN-transform+relu+split on A-load; split output to cat
    gemm_tc<2, 1, 1, 0><<<g1, 256>>>(nullptr, nullptr, P.h, 128,
                                     P.WH + w2off, P.WL + w2off, HH, b2,
                                     P.scale, P.shift,
                                     nullptr, 0, P.catH, P.catL, 384, catcol,
                                     nullptr, nullptr, nullptr, nullptr, NN, 128);
}

extern "C" void kernel_launch(void* const* d_in, const int* in_sizes, int n_in,
                              void* d_out, int out_size)
{
    const float* x  = (const float*)d_in[0];
    const int*   ei = (const int*)d_in[1];

    const float* c1_W1 = (const float*)d_in[2];
    const float* c1_b1 = (const float*)d_in[3];
    const float* c1_g  = (const float*)d_in[4];
    const float* c1_be = (const float*)d_in[5];
    const float* c1_W2 = (const float*)d_in[6];
    const float* c1_b2 = (const float*)d_in[7];

    const float* c2_W1 = (const float*)d_in[8];
    const float* c2_b1 = (const float*)d_in[9];
    const float* c2_g  = (const float*)d_in[10];
    const float* c2_be = (const float*)d_in[11];
    const float* c2_W2 = (const float*)d_in[12];
    const float* c2_b2 = (const float*)d_in[13];

    const float* c3_W1 = (const float*)d_in[14];
    const float* c3_b1 = (const float*)d_in[15];
    const float* c3_g  = (const float*)d_in[16];
    const float* c3_be = (const float*)d_in[17];
    const float* c3_W2 = (const float*)d_in[18];
    const float* c3_b2 = (const float*)d_in[19];

    const float* lin1_W = (const float*)d_in[20];
    const float* lin1_b = (const float*)d_in[21];
    const float* lin2_W = (const float*)d_in[22];
    const float* lin2_b = (const float*)d_in[23];

    Ptrs P;
    cudaGetSymbolAddress((void**)&P.h,     g_h);
    cudaGetSymbolAddress((void**)&P.sum,   g_sum);
    cudaGetSymbolAddress((void**)&P.sumsq, g_sumsq);
    cudaGetSymbolAddress((void**)&P.scale, g_scale);
    cudaGetSymbolAddress((void**)&P.shift, g_shift);
    cudaGetSymbolAddress((void**)&P.aggH,  g_aggH);
    cudaGetSymbolAddress((void**)&P.aggL,  g_aggL);
    cudaGetSymbolAddress((void**)&P.catH,  g_catH);
    cudaGetSymbolAddress((void**)&P.catL,  g_catL);
    cudaGetSymbolAddress((void**)&P.WH,    g_WH);
    cudaGetSymbolAddress((void**)&P.WL,    g_WL);
    cudaGetSymbolAddress((void**)&P.deg,   g_deg);
    cudaGetSymbolAddress((void**)&P.off,   g_off);
    cudaGetSymbolAddress((void**)&P.cur,   g_cur);
    cudaGetSymbolAddress((void**)&P.col,   g_col);

    prep_all<<<(W_TOT + 255) / 256, 256>>>(c1_W1, c1_W2, c2_W1, c2_W2,
                                           c3_W1, c3_W2, lin1_W, P.WH, P.WL);

    cudaMemsetAsync(P.deg, 0, NN * sizeof(int), 0);
    hist_k<<<(EE + 255) / 256, 256>>>(ei, P.deg);
    scan_k<<<1, 1024>>>(P.deg, P.off, P.cur);
    fill_k<<<(EE + 255) / 256, 256>>>(ei, P.cur, P.col);

    run_layer(1, P, W_C1W1, W_C1W2, x, c1_b1, c1_g, c1_be, c1_b2, 0);
    run_layer(2, P, W_C2W1, W_C2W2, nullptr, c2_b1, c2_g, c2_be, c2_b2, HH);
    run_layer(3, P, W_C3W1, W_C3W2, nullptr, c3_b1, c3_g, c3_be, c3_b2, 2 * HH);

    // fused readout: lin1 (relu) + lin2 via atomics, then softmax
    float* out = (float*)d_out;
    init_out_k<<<(NN * 2 + 255) / 256, 256>>>(out, lin2_b);

    dim3 gridL(H3 / BN, MT);
    gemm_tc<0, 1, 2, 0><<<gridL, 256>>>(P.catH, P.catL, nullptr, 384,
                                        P.WH + W_LIN1, P.WL + W_LIN1, H3, lin1_b,
                                        nullptr, nullptr,
                                        nullptr, 0, nullptr, nullptr, 0, 0,
                                        lin2_W, out, nullptr, nullptr, NN, 384);

    int half = out_size / 2;
    softmax_k<<<(NN + 255) / 256, 256>>>(out, half);
}